// round 14
// baseline (speedup 1.0000x reference)
#include <cuda_runtime.h>
#include <cuda_fp16.h>
#include <cstdint>

#define NN   50000
#define EEMAX 800000
#define HIDD 64
#define NH   4
#define SCB  ((NN + 1023) / 1024)   // 49 scan blocks

// frag-major B table offsets (uint2 units; stored pair-packed as uint4)
#define FR_WP    0
#define FR_WGP0  16384
#define FR_WGP1  18432
#define FR_WV0   20480
#define FR_WV1   28672
#define FR_WT    36864
#define FR_TOTAL 47104

// k_mma dynamic smem: double-buffered A (2*128*36 floats) + B (2*1024 uint2)
#define MMA_SMEM (2 * 128 * 36 * 4 + 2 * 1024 * 8)

// ---------------- scratch (device globals; no allocations allowed) ----------------
__device__ int   g_deg[NN];
__device__ int   g_rowptr[NN + 1];
__device__ int   g_cursor[NN];
__device__ int   g_part[64];
__device__ int   g_col[EEMAX];
__device__ __align__(16) uint2 g_bfrag[FR_TOTAL];
__device__ __align__(16) float g_hcat[NN * 320];    // [n][0:64)=proj, [64:320)=layer1 gated heads
__device__ __align__(16) float g_curA[NN * HIDD];
__device__ __align__(16) float g_el[NN * NH];
__device__ __align__(16) float g_er[NN * NH];
__device__ __align__(16) float g_acc[NN * NH * HIDD];
__device__ __align__(16) uint2 g_h2[NN * 32];       // [n][lane] = {cur half2, pooled half2}
__device__ float g_bl[2 * NH * HIDD];               // both layers
__device__ float g_br[2 * NH * HIDD];

__device__ __forceinline__ float lrelu(float x, float s) { return x > 0.f ? x : s * x; }

// ---------------- tf32 helpers ----------------
__device__ __forceinline__ void split_tf32(float x, uint32_t& hi, uint32_t& lo) {
    asm("cvt.rna.tf32.f32 %0, %1;" : "=r"(hi) : "f"(x));
    float r = x - __uint_as_float(hi);
    asm("cvt.rna.tf32.f32 %0, %1;" : "=r"(lo) : "f"(r));
}

__device__ __forceinline__ uint32_t to_tf32(float x) {
    uint32_t h;
    asm("cvt.rna.tf32.f32 %0, %1;" : "=r"(h) : "f"(x));
    return h;
}

__device__ __forceinline__ void mma8(float* d,
                                     uint32_t a0, uint32_t a1, uint32_t a2, uint32_t a3,
                                     uint32_t b0, uint32_t b1) {
    asm volatile(
        "mma.sync.aligned.m16n8k8.row.col.f32.tf32.tf32.f32 "
        "{%0,%1,%2,%3},{%4,%5,%6,%7},{%8,%9},{%0,%1,%2,%3};"
        : "+f"(d[0]), "+f"(d[1]), "+f"(d[2]), "+f"(d[3])
        : "r"(a0), "r"(a1), "r"(a2), "r"(a3), "r"(b0), "r"(b1));
}

// ---------------- CSR build ----------------
__global__ void k_zero_deg() {
    int i = blockIdx.x * blockDim.x + threadIdx.x;
    if (i < NN) g_deg[i] = 0;
}

__global__ void k_deg(const int* __restrict__ dst, int ne) {
    int e = blockIdx.x * blockDim.x + threadIdx.x;
    if (e < ne) atomicAdd(&g_deg[dst[e]], 1);
}

__global__ __launch_bounds__(1024) void k_scan1() {
    __shared__ int sh[32];
    int tid = threadIdx.x, lane = tid & 31, wid = tid >> 5;
    int i = blockIdx.x * 1024 + tid;
    int v = (i < NN) ? g_deg[i] : 0;
    #pragma unroll
    for (int o = 16; o; o >>= 1) v += __shfl_xor_sync(0xffffffffu, v, o);
    if (lane == 0) sh[wid] = v;
    __syncthreads();
    if (tid < 32) {
        int t = sh[tid];
        #pragma unroll
        for (int o = 16; o; o >>= 1) t += __shfl_xor_sync(0xffffffffu, t, o);
        if (tid == 0) g_part[blockIdx.x] = t;
    }
}

__global__ void k_scan2() {
    __shared__ int sh[64];
    int tid = threadIdx.x;
    int v = (tid < SCB) ? g_part[tid] : 0;
    sh[tid] = v;
    __syncthreads();
    #pragma unroll
    for (int off = 1; off < 64; off <<= 1) {
        int t = (tid >= off) ? sh[tid - off] : 0;
        __syncthreads();
        sh[tid] += t;
        __syncthreads();
    }
    if (tid < SCB) g_part[tid] = sh[tid] - v;
    if (tid == SCB - 1) g_rowptr[NN] = sh[tid];
}

__global__ __launch_bounds__(1024) void k_scan3() {
    __shared__ int sh[1024];
    int tid = threadIdx.x;
    int i = blockIdx.x * 1024 + tid;
    int v = (i < NN) ? g_deg[i] : 0;
    sh[tid] = v;
    __syncthreads();
    #pragma unroll
    for (int off = 1; off < 1024; off <<= 1) {
        int t = (tid >= off) ? sh[tid - off] : 0;
        __syncthreads();
        sh[tid] += t;
        __syncthreads();
    }
    if (i < NN) {
        int excl = sh[tid] - v + g_part[blockIdx.x];
        g_rowptr[i] = excl;
        g_cursor[i] = excl;
    }
}

__global__ void k_fill(const int* __restrict__ src, const int* __restrict__ dst, int ne) {
    int e = blockIdx.x * blockDim.x + threadIdx.x;
    if (e < ne) {
        int p = atomicAdd(&g_cursor[dst[e]], 1);
        g_col[p] = src[e];
    }
}

// ---------------- one-time: convert weights into PAIR-PACKED frag-major tf32-hi table ----------------
// uint4 at index ((k8*4+np)*32+lane) = {b[nt=2np].x, .y, b[nt=2np+1].x, .y}
__global__ void k_splitAll(const float* __restrict__ Wp, const float* __restrict__ Wgp,
                           const float* __restrict__ Wv, const float* __restrict__ Wt) {
    int v4 = blockIdx.x * 256 + threadIdx.x;       // uint4 index, [0, FR_TOTAL/2)
    if (v4 >= FR_TOTAL / 2) return;
    int u = v4 * 2;                                 // uint2 offset for region lookup
    const float* src; int off;
    if (u < FR_WGP0)      { src = Wp;         off = FR_WP;   }
    else if (u < FR_WGP1) { src = Wgp;        off = FR_WGP0; }
    else if (u < FR_WV0)  { src = Wgp + 4096; off = FR_WGP1; }
    else if (u < FR_WV1)  { src = Wv;         off = FR_WV0;  }
    else if (u < FR_WT)   { src = Wv + 16384; off = FR_WV1;  }
    else                  { src = Wt;         off = FR_WT;   }
    int local = v4 - off / 2;                       // uint4-local index within region
    int k8 = local >> 7, rem = local & 127;
    int np = rem >> 5, lane = rem & 31;
    int g = lane >> 2, t4 = lane & 3;
    int col0 = (2 * np) * 8 + g, col1 = (2 * np + 1) * 8 + g;
    float v00 = src[(k8 * 8 + t4) * 64 + col0];
    float v01 = src[(k8 * 8 + t4 + 4) * 64 + col0];
    float v10 = src[(k8 * 8 + t4) * 64 + col1];
    float v11 = src[(k8 * 8 + t4 + 4) * 64 + col1];
    ((uint4*)g_bfrag)[v4] = make_uint4(to_tf32(v00), to_tf32(v01), to_tf32(v10), to_tf32(v11));
}

// ---------------- tensor-core GEMM: C[M,64] = f(A[M,K] @ B[K,64]) ----------------
// PASSES=2: (ah+al)*bh; PASSES=1: ah*bh only.
// mode 0: C = v (+bias); mode 1: C = lrelu(scale*v); mode 2: g_h2[..].y = half2(v) (pooled path)
template <int PASSES>
__global__ __launch_bounds__(256, 3) void k_mma(
    const float* __restrict__ A, int lda, int aBS,
    const uint2* __restrict__ Bf, int bFS,
    float* __restrict__ C, int ldc, int cBS,
    int M, int K, const float* __restrict__ bias, int mode, float scale)
{
    extern __shared__ char smem_raw[];
    float (*As)[128][36] = reinterpret_cast<float(*)[128][36]>(smem_raw);
    uint2* Bs = reinterpret_cast<uint2*>(smem_raw + 2 * 128 * 36 * 4);
    const float* Ab  = A  + (size_t)blockIdx.z * aBS;
    const uint2* Bfb = Bf + (size_t)blockIdx.z * bFS;
    float*       Cb  = C  + (size_t)blockIdx.z * cBS;
    int row0 = blockIdx.x * 128;
    int tid = threadIdx.x, w = tid >> 5, lane = tid & 31;
    int g = lane >> 2, t4 = lane & 3;
    int sk = (tid & 7) * 4, srr = tid >> 3;

    float d[8][4];
    #pragma unroll
    for (int i = 0; i < 8; i++)
        #pragma unroll
        for (int j = 0; j < 4; j++) d[i][j] = 0.f;

    auto stage = [&](int buf, int kk) {
        #pragma unroll
        for (int p = 0; p < 4; p++) {
            int r = p * 32 + srr;
            int gr = row0 + r;
            uint32_t sa = (uint32_t)__cvta_generic_to_shared(&As[buf][r][sk]);
            const float* gp = Ab + (size_t)gr * lda + kk + sk;
            int sz = (gr < M) ? 16 : 0;
            asm volatile("cp.async.cg.shared.global [%0], [%1], 16, %2;\n"
                         :: "r"(sa), "l"(gp), "r"(sz));
        }
        const uint2* bsrc = Bfb + (size_t)(kk >> 3) * 256 + tid;
        #pragma unroll
        for (int j = 0; j < 4; j++) {
            uint32_t sa = (uint32_t)__cvta_generic_to_shared(&Bs[buf * 1024 + tid + 256 * j]);
            asm volatile("cp.async.ca.shared.global [%0], [%1], 8;\n"
                         :: "r"(sa), "l"(bsrc + 256 * j));
        }
        asm volatile("cp.async.commit_group;\n");
    };

    stage(0, 0);
    int buf = 0;
    for (int kk = 0; kk < K; kk += 32) {
        if (kk + 32 < K) {
            stage(buf ^ 1, kk + 32);
            asm volatile("cp.async.wait_group 1;\n");
        } else {
            asm volatile("cp.async.wait_group 0;\n");
        }
        __syncthreads();

        const uint4* Bs4 = (const uint4*)(Bs + buf * 1024);
        #pragma unroll
        for (int k8 = 0; k8 < 4; k8++) {
            int kb = k8 * 8;
            float a0 = As[buf][w * 16 + g][kb + t4];
            float a1 = As[buf][w * 16 + g + 8][kb + t4];
            float a2 = As[buf][w * 16 + g][kb + t4 + 4];
            float a3 = As[buf][w * 16 + g + 8][kb + t4 + 4];
            uint32_t ah0, al0, ah1, al1, ah2, al2, ah3, al3;
            if (PASSES == 2) {
                split_tf32(a0, ah0, al0);
                split_tf32(a1, ah1, al1);
                split_tf32(a2, ah2, al2);
                split_tf32(a3, ah3, al3);
            } else {
                ah0 = to_tf32(a0); ah1 = to_tf32(a1);
                ah2 = to_tf32(a2); ah3 = to_tf32(a3);
            }
            #pragma unroll
            for (int np = 0; np < 4; np++) {
                uint4 bb = Bs4[(k8 * 4 + np) * 32 + lane];
                if (PASSES == 2) {
                    mma8(d[2 * np],     al0, al1, al2, al3, bb.x, bb.y);
                    mma8(d[2 * np + 1], al0, al1, al2, al3, bb.z, bb.w);
                }
                mma8(d[2 * np],     ah0, ah1, ah2, ah3, bb.x, bb.y);
                mma8(d[2 * np + 1], ah0, ah1, ah2, ah3, bb.z, bb.w);
            }
        }
        __syncthreads();   // protect buf before it is re-staged next iteration
        buf ^= 1;
    }

    int rb = row0 + w * 16;
    int rA = rb + g, rB = rb + g + 8;
    #pragma unroll
    for (int nt = 0; nt < 8; nt++) {
        int c = nt * 8 + t4 * 2;
        if (rA < M) {
            float2 v = make_float2(d[nt][0], d[nt][1]);
            if (mode == 2) {
                __half2 hh = __floats2half2_rn(v.x, v.y);
                ((uint32_t*)Cb)[((size_t)rA * 32 + (c >> 1)) * 2 + 1] = *(uint32_t*)&hh;
            } else {
                if (mode == 1) { v.x = lrelu(scale * v.x, 0.01f); v.y = lrelu(scale * v.y, 0.01f); }
                else if (bias) { v.x += bias[c]; v.y += bias[c + 1]; }
                *(float2*)&Cb[(size_t)rA * ldc + c] = v;
            }
        }
        if (rB < M) {
            float2 v = make_float2(d[nt][2], d[nt][3]);
            if (mode == 2) {
                __half2 hh = __floats2half2_rn(v.x, v.y);
                ((uint32_t*)Cb)[((size_t)rB * 32 + (c >> 1)) * 2 + 1] = *(uint32_t*)&hh;
            } else {
                if (mode == 1) { v.x = lrelu(scale * v.x, 0.01f); v.y = lrelu(scale * v.y, 0.01f); }
                else if (bias) { v.x += bias[c]; v.y += bias[c + 1]; }
                *(float2*)&Cb[(size_t)rB * ldc + c] = v;
            }
        }
    }
}

// ---------------- both layers at once: bl[i][h]=We@a_l[i,h], br[i][h]=We@a_r[i,h] ----------------
__global__ void k_vecs2(const float* __restrict__ We,
                        const float* __restrict__ al, const float* __restrict__ ar) {
    int i = blockIdx.x;             // layer
    int t = threadIdx.x;
    int h = t >> 6, k = t & 63;
    float sl = 0.f, sr = 0.f;
    #pragma unroll 8
    for (int d = 0; d < 64; d++) {
        float w = We[k * 64 + d];
        sl += w * al[i * 256 + h * 64 + d];
        sr += w * ar[i * 256 + h * 64 + d];
    }
    g_bl[i * 256 + h * 64 + k] = sl;
    g_br[i * 256 + h * 64 + k] = sr;
}

// ---------------- prep: fp16 pack of cur (x-word only) + el/er dots. warp per node ----------------
__global__ __launch_bounds__(256) void k_prep(const float* __restrict__ cur, int lda, int layer) {
    __shared__ float blS[256], brS[256];
    int tid = threadIdx.x;
    blS[tid] = g_bl[layer * 256 + tid];
    brS[tid] = g_br[layer * 256 + tid];
    __syncthreads();
    int w = tid >> 5, lane = tid & 31;
    int n = blockIdx.x * 8 + w;
    float2 c = *(const float2*)&cur[(size_t)n * lda + lane * 2];
    __half2 ch = __floats2half2_rn(c.x, c.y);
    ((uint32_t*)&g_h2[n * 32 + lane])[0] = *(uint32_t*)&ch;   // .y (pooled) written by GEMM mode 2
    float p[8];
    #pragma unroll
    for (int h = 0; h < 4; h++) {
        p[h]     = c.x * blS[h * 64 + 2 * lane] + c.y * blS[h * 64 + 2 * lane + 1];
        p[4 + h] = c.x * brS[h * 64 + 2 * lane] + c.y * brS[h * 64 + 2 * lane + 1];
    }
    #pragma unroll
    for (int o = 16; o; o >>= 1) {
        #pragma unroll
        for (int q = 0; q < 8; q++) p[q] += __shfl_xor_sync(0xffffffffu, p[q], o);
    }
    if (lane == 0) {
        ((float4*)g_el)[n] = make_float4(p[0], p[1], p[2], p[3]);
        ((float4*)g_er)[n] = make_float4(p[4], p[5], p[6], p[7]);
    }
}

// ---------------- fused per-dst softmax (no-max) + aggregation + GaAN gate (pre-applied) ----------------
// Warp per dst. Interleaved 8B gathers with +1 software prefetch (MLP=2). No atomics.
__global__ __launch_bounds__(256) void k_agg(const float* __restrict__ Wg,
                                             const float* __restrict__ bg) {
    __shared__ float  WgS[768];
    __shared__ int    ssh[8][33];
    __shared__ float4 wsh[8][32];
    int tid = threadIdx.x, w = tid >> 5, lane = tid & 31;
    #pragma unroll
    for (int i = 0; i < 3; i++) WgS[tid + 256 * i] = Wg[tid + 256 * i];
    ssh[w][lane] = 0;
    if (lane == 0) ssh[w][32] = 0;
    __syncthreads();
    int d = blockIdx.x * 8 + w;
    int r0 = g_rowptr[d], r1 = g_rowptr[d + 1];
    float4 erv = ((const float4*)g_er)[d];

    float s0 = 0.f, s1 = 0.f, s2 = 0.f, s3 = 0.f;
    float2 a0 = {0, 0}, a1 = {0, 0}, a2 = {0, 0}, a3 = {0, 0}, am = {0, 0};
    float2 amx = {-1e30f, -1e30f};
    int l2 = lane * 2;
    for (int base = r0; base < r1; base += 32) {
        int cnt = min(32, r1 - base);
        if (lane < cnt) {
            int s = g_col[base + lane];
            float4 e = ((const float4*)g_el)[s];
            float4 wv;
            wv.x = __expf(lrelu(e.x + erv.x, 0.2f));
            wv.y = __expf(lrelu(e.y + erv.y, 0.2f));
            wv.z = __expf(lrelu(e.z + erv.z, 0.2f));
            wv.w = __expf(lrelu(e.w + erv.w, 0.2f));
            s0 += wv.x; s1 += wv.y; s2 += wv.z; s3 += wv.w;
            ssh[w][lane] = s;
            wsh[w][lane] = wv;
        }
        __syncwarp();
        uint2 hv = __ldg(&g_h2[(size_t)ssh[w][0] * 32 + lane]);
        for (int t = 0; t < cnt; t++) {
            uint2 cv = hv;
            hv = __ldg(&g_h2[(size_t)ssh[w][t + 1] * 32 + lane]);  // prefetch next edge
            float4 wv = wsh[w][t];
            float2 c  = __half22float2(*(__half2*)&cv.x);
            float2 pp = __half22float2(*(__half2*)&cv.y);
            a0.x += wv.x * c.x; a0.y += wv.x * c.y;
            a1.x += wv.y * c.x; a1.y += wv.y * c.y;
            a2.x += wv.z * c.x; a2.y += wv.z * c.y;
            a3.x += wv.w * c.x; a3.y += wv.w * c.y;
            am.x += c.x;        am.y += c.y;
            amx.x = fmaxf(amx.x, pp.x);
            amx.y = fmaxf(amx.y, pp.y);
        }
        __syncwarp();
    }
    #pragma unroll
    for (int o = 16; o; o >>= 1) {
        s0 += __shfl_xor_sync(0xffffffffu, s0, o);
        s1 += __shfl_xor_sync(0xffffffffu, s1, o);
        s2 += __shfl_xor_sync(0xffffffffu, s2, o);
        s3 += __shfl_xor_sync(0xffffffffu, s3, o);
    }
    float dinv = 1.f / (float)(r1 - r0);

    // GaAN gate: g = sigmoid([cur_d, mx, mn] @ Wg + bg)
    float2 cd = __half22float2(*(__half2*)&g_h2[(size_t)d * 32 + lane].x);
    float gin[6] = {cd.x, cd.y, amx.x, amx.y, am.x * dinv, am.y * dinv};
    int   kbase[3] = {l2, 64 + l2, 128 + l2};
    float gp0 = 0.f, gp1 = 0.f, gp2 = 0.f, gp3 = 0.f;
    #pragma unroll
    for (int q = 0; q < 3; q++) {
        #pragma unroll
        for (int e2 = 0; e2 < 2; e2++) {
            float v = gin[q * 2 + e2];
            float4 wr = *(const float4*)&WgS[(kbase[q] + e2) * 4];
            gp0 += v * wr.x; gp1 += v * wr.y; gp2 += v * wr.z; gp3 += v * wr.w;
        }
    }
    #pragma unroll
    for (int o = 16; o; o >>= 1) {
        gp0 += __shfl_xor_sync(0xffffffffu, gp0, o);
        gp1 += __shfl_xor_sync(0xffffffffu, gp1, o);
        gp2 += __shfl_xor_sync(0xffffffffu, gp2, o);
        gp3 += __shfl_xor_sync(0xffffffffu, gp3, o);
    }
    float g0 = 1.f / (1.f + __expf(-(gp0 + bg[0])));
    float g1 = 1.f / (1.f + __expf(-(gp1 + bg[1])));
    float g2 = 1.f / (1.f + __expf(-(gp2 + bg[2])));
    float g3 = 1.f / (1.f + __expf(-(gp3 + bg[3])));

    float i0 = g0 / s0, i1 = g1 / s1, i2 = g2 / s2, i3 = g3 / s3;
    float* ap = &g_acc[d * 256];
    *(float2*)&ap[l2]       = make_float2(a0.x * i0, a0.y * i0);
    *(float2*)&ap[64 + l2]  = make_float2(a1.x * i1, a1.y * i1);
    *(float2*)&ap[128 + l2] = make_float2(a2.x * i2, a2.y * i2);
    *(float2*)&ap[192 + l2] = make_float2(a3.x * i3, a3.y * i3);
}

// ---------------- launch ----------------
extern "C" void kernel_launch(void* const* d_in, const int* in_sizes, int n_in,
                              void* d_out, int out_size) {
    const float* ft    = (const float*)d_in[0];
    const float* Wp    = (const float*)d_in[1];
    const float* We    = (const float*)d_in[2];
    const float* a_l   = (const float*)d_in[3];
    const float* a_r   = (const float*)d_in[4];
    const float* Wv    = (const float*)d_in[5];
    const float* Wgp   = (const float*)d_in[6];
    const float* Wgate = (const float*)d_in[7];
    const float* bgate = (const float*)d_in[8];
    const float* Wtran = (const float*)d_in[9];
    const float* btran = (const float*)d_in[10];
    const int*   src   = (const int*)d_in[11];
    const int*   dst   = (const int*)d_in[12];
    int ne = in_sizes[11];
    float* out = (float*)d_out;

    float *p_hcat, *p_curA, *p_acc;
    uint2* p_bfrag;
    uint2* p_h2;
    cudaGetSymbolAddress((void**)&p_hcat, g_hcat);
    cudaGetSymbolAddress((void**)&p_curA, g_curA);
    cudaGetSymbolAddress((void**)&p_acc, g_acc);
    cudaGetSymbolAddress((void**)&p_bfrag, g_bfrag);
    cudaGetSymbolAddress((void**)&p_h2, g_h2);

    cudaFuncSetAttribute(k_mma<2>, cudaFuncAttributeMaxDynamicSharedMemorySize, MMA_SMEM);
    cudaFuncSetAttribute(k_mma<1>, cudaFuncAttributeMaxDynamicSharedMemorySize, MMA_SMEM);

    const int MB = (NN + 127) / 128;  // 391
    int eb = (ne + 255) / 256;

    // slots 1-3
    k_zero_deg<<<(NN + 255) / 256, 256>>>();
    k_deg<<<eb, 256>>>(dst, ne);
    k_splitAll<<<(FR_TOTAL / 2 + 255) / 256, 256>>>(Wp, Wgp, Wv, Wtran);
    // slot 4: proj GEMM (profiled launch), 1xTF32 -- proj_feat = ft @ Wp -> hcat[:,0:64)
    k_mma<1><<<dim3(MB, 1, 1), 256, MMA_SMEM>>>(ft, 512, 0, p_bfrag + FR_WP, 0, p_hcat, 320, 0, NN, 512, nullptr, 0, 1.f);
    // CSR + per-layer attention vectors
    k_scan1<<<SCB, 1024>>>();
    k_scan2<<<1, 64>>>();
    k_scan3<<<SCB, 1024>>>();
    k_fill<<<eb, 256>>>(src, dst, ne);
    k_vecs2<<<2, 256>>>(We, a_l, a_r);

    for (int i = 0; i < 2; i++) {
        const float* cur = i ? p_curA : p_hcat;
        int lda = i ? 64 : 320;
        // pooled = cur @ Wg_pool[i], written as fp16 straight into g_h2[..].y (mode 2, 1xTF32)
        k_mma<1><<<dim3(MB, 1, 1), 256, MMA_SMEM>>>(cur, lda, 0, p_bfrag + (i ? FR_WGP1 : FR_WGP0), 0,
                                                    (float*)p_h2, 0, 0, NN, 64, nullptr, 2, 1.f);
        k_prep<<<6250, 256>>>(cur, lda, i);
        k_agg<<<6250, 256>>>(Wgate + i * 768, bgate + i * 4);
        if (i == 0) {
            // cur1 = lrelu(0.25 * acc_gated @ Wv0_stacked[256,64])  (1xTF32)
            k_mma<1><<<dim3(MB, 1, 1), 256, MMA_SMEM>>>(p_acc, 256, 0, p_bfrag + FR_WV0, 0,
                                                        p_curA, 64, 0, NN, 256, nullptr, 1, 0.25f);
        } else {
            // hcat[:,64+h*64+:] = lrelu(acc_gated[:,h,:] @ Wv1_h)   (2xTF32, batched over heads)
            k_mma<2><<<dim3(MB, 1, 4), 256, MMA_SMEM>>>(p_acc, 256, 64, p_bfrag + FR_WV1, 2048,
                                                        p_hcat + 64, 320, 64, NN, 64, nullptr, 1, 1.f);
        }
    }

    // out = hcat[N,320] @ Wtran[320,64] + btran  (1xTF32)
    k_mma<1><<<dim3(MB, 1, 1), 256, MMA_SMEM>>>(p_hcat, 320, 0, p_bfrag + FR_WT, 0, out, 64, 0, NN, 320, btran, 0, 1.f);
}

// round 15
// speedup vs baseline: 1.0650x; 1.0650x over previous
#include <cuda_runtime.h>
#include <cuda_fp16.h>
#include <cstdint>

#define NN   50000
#define EEMAX 800000
#define HIDD 64
#define NH   4
#define SCB  ((NN + 1023) / 1024)   // 49 scan blocks

// frag-major B table offsets (uint2 units; stored pair-packed as uint4)
#define FR_WP    0
#define FR_WGP0  16384
#define FR_WGP1  18432
#define FR_WV0   20480
#define FR_WV1   28672
#define FR_WT    36864
#define FR_TOTAL 47104

// k_mma dynamic smem: double-buffered A (2*128*36 floats) + B (2*1024 uint2)
#define MMA_SMEM (2 * 128 * 36 * 4 + 2 * 1024 * 8)

// ---------------- scratch (device globals; no allocations allowed) ----------------
__device__ int   g_deg[NN];
__device__ int   g_rowptr[NN + 1];
__device__ int   g_cursor[NN];
__device__ int   g_part[64];
__device__ int   g_col[EEMAX];
__device__ __align__(16) uint2 g_bfrag[FR_TOTAL];
__device__ __align__(16) float g_hcat[NN * 320];    // [n][0:64)=proj, [64:320)=layer1 gated heads
__device__ __align__(16) float g_curA[NN * HIDD];
__device__ __align__(16) float g_el[NN * NH];
__device__ __align__(16) float g_er[NN * NH];
__device__ __align__(16) float g_acc[NN * NH * HIDD];
__device__ __align__(16) uint2 g_h2[NN * 32];       // [n][lane] = {cur half2, pooled half2}
__device__ float g_bl[2 * NH * HIDD];               // both layers
__device__ float g_br[2 * NH * HIDD];

__device__ __forceinline__ float lrelu(float x, float s) { return x > 0.f ? x : s * x; }

// ---------------- tf32 helpers ----------------
__device__ __forceinline__ void split_tf32(float x, uint32_t& hi, uint32_t& lo) {
    asm("cvt.rna.tf32.f32 %0, %1;" : "=r"(hi) : "f"(x));
    float r = x - __uint_as_float(hi);
    asm("cvt.rna.tf32.f32 %0, %1;" : "=r"(lo) : "f"(r));
}

__device__ __forceinline__ uint32_t to_tf32(float x) {
    uint32_t h;
    asm("cvt.rna.tf32.f32 %0, %1;" : "=r"(h) : "f"(x));
    return h;
}

__device__ __forceinline__ void mma8(float* d,
                                     uint32_t a0, uint32_t a1, uint32_t a2, uint32_t a3,
                                     uint32_t b0, uint32_t b1) {
    asm volatile(
        "mma.sync.aligned.m16n8k8.row.col.f32.tf32.tf32.f32 "
        "{%0,%1,%2,%3},{%4,%5,%6,%7},{%8,%9},{%0,%1,%2,%3};"
        : "+f"(d[0]), "+f"(d[1]), "+f"(d[2]), "+f"(d[3])
        : "r"(a0), "r"(a1), "r"(a2), "r"(a3), "r"(b0), "r"(b1));
}

// ---------------- CSR build ----------------
__global__ void k_zero_deg() {
    int i = blockIdx.x * blockDim.x + threadIdx.x;
    if (i < NN) g_deg[i] = 0;
}

__global__ void k_deg(const int* __restrict__ dst, int ne) {
    int e = blockIdx.x * blockDim.x + threadIdx.x;
    if (e < ne) atomicAdd(&g_deg[dst[e]], 1);
}

__global__ __launch_bounds__(1024) void k_scan1() {
    __shared__ int sh[32];
    int tid = threadIdx.x, lane = tid & 31, wid = tid >> 5;
    int i = blockIdx.x * 1024 + tid;
    int v = (i < NN) ? g_deg[i] : 0;
    #pragma unroll
    for (int o = 16; o; o >>= 1) v += __shfl_xor_sync(0xffffffffu, v, o);
    if (lane == 0) sh[wid] = v;
    __syncthreads();
    if (tid < 32) {
        int t = sh[tid];
        #pragma unroll
        for (int o = 16; o; o >>= 1) t += __shfl_xor_sync(0xffffffffu, t, o);
        if (tid == 0) g_part[blockIdx.x] = t;
    }
}

__global__ void k_scan2() {
    __shared__ int sh[64];
    int tid = threadIdx.x;
    int v = (tid < SCB) ? g_part[tid] : 0;
    sh[tid] = v;
    __syncthreads();
    #pragma unroll
    for (int off = 1; off < 64; off <<= 1) {
        int t = (tid >= off) ? sh[tid - off] : 0;
        __syncthreads();
        sh[tid] += t;
        __syncthreads();
    }
    if (tid < SCB) g_part[tid] = sh[tid] - v;
    if (tid == SCB - 1) g_rowptr[NN] = sh[tid];
}

__global__ __launch_bounds__(1024) void k_scan3() {
    __shared__ int sh[1024];
    int tid = threadIdx.x;
    int i = blockIdx.x * 1024 + tid;
    int v = (i < NN) ? g_deg[i] : 0;
    sh[tid] = v;
    __syncthreads();
    #pragma unroll
    for (int off = 1; off < 1024; off <<= 1) {
        int t = (tid >= off) ? sh[tid - off] : 0;
        __syncthreads();
        sh[tid] += t;
        __syncthreads();
    }
    if (i < NN) {
        int excl = sh[tid] - v + g_part[blockIdx.x];
        g_rowptr[i] = excl;
        g_cursor[i] = excl;
    }
}

__global__ void k_fill(const int* __restrict__ src, const int* __restrict__ dst, int ne) {
    int e = blockIdx.x * blockDim.x + threadIdx.x;
    if (e < ne) {
        int p = atomicAdd(&g_cursor[dst[e]], 1);
        g_col[p] = src[e];
    }
}

// ---------------- one-time: convert weights into PAIR-PACKED frag-major tf32-hi table ----------------
// uint4 at index ((k8*4+np)*32+lane) = {b[nt=2np].x, .y, b[nt=2np+1].x, .y}
__global__ void k_splitAll(const float* __restrict__ Wp, const float* __restrict__ Wgp,
                           const float* __restrict__ Wv, const float* __restrict__ Wt) {
    int v4 = blockIdx.x * 256 + threadIdx.x;       // uint4 index, [0, FR_TOTAL/2)
    if (v4 >= FR_TOTAL / 2) return;
    int u = v4 * 2;                                 // uint2 offset for region lookup
    const float* src; int off;
    if (u < FR_WGP0)      { src = Wp;         off = FR_WP;   }
    else if (u < FR_WGP1) { src = Wgp;        off = FR_WGP0; }
    else if (u < FR_WV0)  { src = Wgp + 4096; off = FR_WGP1; }
    else if (u < FR_WV1)  { src = Wv;         off = FR_WV0;  }
    else if (u < FR_WT)   { src = Wv + 16384; off = FR_WV1;  }
    else                  { src = Wt;         off = FR_WT;   }
    int local = v4 - off / 2;                       // uint4-local index within region
    int k8 = local >> 7, rem = local & 127;
    int np = rem >> 5, lane = rem & 31;
    int g = lane >> 2, t4 = lane & 3;
    int col0 = (2 * np) * 8 + g, col1 = (2 * np + 1) * 8 + g;
    float v00 = src[(k8 * 8 + t4) * 64 + col0];
    float v01 = src[(k8 * 8 + t4 + 4) * 64 + col0];
    float v10 = src[(k8 * 8 + t4) * 64 + col1];
    float v11 = src[(k8 * 8 + t4 + 4) * 64 + col1];
    ((uint4*)g_bfrag)[v4] = make_uint4(to_tf32(v00), to_tf32(v01), to_tf32(v10), to_tf32(v11));
}

// ---------------- tensor-core GEMM: C[M,64] = f(A[M,K] @ B[K,64]) ----------------
// PASSES=2: (ah+al)*bh; PASSES=1: ah*bh only.
// mode 0: C = v (+bias); mode 1: C = lrelu(scale*v); mode 2: g_h2[..].y = half2(v) (pooled path)
template <int PASSES>
__global__ __launch_bounds__(256, 3) void k_mma(
    const float* __restrict__ A, int lda, int aBS,
    const uint2* __restrict__ Bf, int bFS,
    float* __restrict__ C, int ldc, int cBS,
    int M, int K, const float* __restrict__ bias, int mode, float scale)
{
    extern __shared__ char smem_raw[];
    float (*As)[128][36] = reinterpret_cast<float(*)[128][36]>(smem_raw);
    uint2* Bs = reinterpret_cast<uint2*>(smem_raw + 2 * 128 * 36 * 4);
    const float* Ab  = A  + (size_t)blockIdx.z * aBS;
    const uint2* Bfb = Bf + (size_t)blockIdx.z * bFS;
    float*       Cb  = C  + (size_t)blockIdx.z * cBS;
    int row0 = blockIdx.x * 128;
    int tid = threadIdx.x, w = tid >> 5, lane = tid & 31;
    int g = lane >> 2, t4 = lane & 3;
    int sk = (tid & 7) * 4, srr = tid >> 3;

    float d[8][4];
    #pragma unroll
    for (int i = 0; i < 8; i++)
        #pragma unroll
        for (int j = 0; j < 4; j++) d[i][j] = 0.f;

    auto stage = [&](int buf, int kk) {
        #pragma unroll
        for (int p = 0; p < 4; p++) {
            int r = p * 32 + srr;
            int gr = row0 + r;
            uint32_t sa = (uint32_t)__cvta_generic_to_shared(&As[buf][r][sk]);
            const float* gp = Ab + (size_t)gr * lda + kk + sk;
            int sz = (gr < M) ? 16 : 0;
            asm volatile("cp.async.cg.shared.global [%0], [%1], 16, %2;\n"
                         :: "r"(sa), "l"(gp), "r"(sz));
        }
        const uint2* bsrc = Bfb + (size_t)(kk >> 3) * 256 + tid;
        #pragma unroll
        for (int j = 0; j < 4; j++) {
            uint32_t sa = (uint32_t)__cvta_generic_to_shared(&Bs[buf * 1024 + tid + 256 * j]);
            asm volatile("cp.async.ca.shared.global [%0], [%1], 8;\n"
                         :: "r"(sa), "l"(bsrc + 256 * j));
        }
        asm volatile("cp.async.commit_group;\n");
    };

    stage(0, 0);
    int buf = 0;
    for (int kk = 0; kk < K; kk += 32) {
        if (kk + 32 < K) {
            stage(buf ^ 1, kk + 32);
            asm volatile("cp.async.wait_group 1;\n");
        } else {
            asm volatile("cp.async.wait_group 0;\n");
        }
        __syncthreads();

        const uint4* Bs4 = (const uint4*)(Bs + buf * 1024);
        #pragma unroll
        for (int k8 = 0; k8 < 4; k8++) {
            int kb = k8 * 8;
            float a0 = As[buf][w * 16 + g][kb + t4];
            float a1 = As[buf][w * 16 + g + 8][kb + t4];
            float a2 = As[buf][w * 16 + g][kb + t4 + 4];
            float a3 = As[buf][w * 16 + g + 8][kb + t4 + 4];
            uint32_t ah0, al0, ah1, al1, ah2, al2, ah3, al3;
            if (PASSES == 2) {
                split_tf32(a0, ah0, al0);
                split_tf32(a1, ah1, al1);
                split_tf32(a2, ah2, al2);
                split_tf32(a3, ah3, al3);
            } else {
                ah0 = to_tf32(a0); ah1 = to_tf32(a1);
                ah2 = to_tf32(a2); ah3 = to_tf32(a3);
            }
            #pragma unroll
            for (int np = 0; np < 4; np++) {
                uint4 bb = Bs4[(k8 * 4 + np) * 32 + lane];
                if (PASSES == 2) {
                    mma8(d[2 * np],     al0, al1, al2, al3, bb.x, bb.y);
                    mma8(d[2 * np + 1], al0, al1, al2, al3, bb.z, bb.w);
                }
                mma8(d[2 * np],     ah0, ah1, ah2, ah3, bb.x, bb.y);
                mma8(d[2 * np + 1], ah0, ah1, ah2, ah3, bb.z, bb.w);
            }
        }
        __syncthreads();   // protect buf before it is re-staged next iteration
        buf ^= 1;
    }

    int rb = row0 + w * 16;
    int rA = rb + g, rB = rb + g + 8;
    #pragma unroll
    for (int nt = 0; nt < 8; nt++) {
        int c = nt * 8 + t4 * 2;
        if (rA < M) {
            float2 v = make_float2(d[nt][0], d[nt][1]);
            if (mode == 2) {
                __half2 hh = __floats2half2_rn(v.x, v.y);
                ((uint32_t*)Cb)[((size_t)rA * 32 + (c >> 1)) * 2 + 1] = *(uint32_t*)&hh;
            } else {
                if (mode == 1) { v.x = lrelu(scale * v.x, 0.01f); v.y = lrelu(scale * v.y, 0.01f); }
                else if (bias) { v.x += bias[c]; v.y += bias[c + 1]; }
                *(float2*)&Cb[(size_t)rA * ldc + c] = v;
            }
        }
        if (rB < M) {
            float2 v = make_float2(d[nt][2], d[nt][3]);
            if (mode == 2) {
                __half2 hh = __floats2half2_rn(v.x, v.y);
                ((uint32_t*)Cb)[((size_t)rB * 32 + (c >> 1)) * 2 + 1] = *(uint32_t*)&hh;
            } else {
                if (mode == 1) { v.x = lrelu(scale * v.x, 0.01f); v.y = lrelu(scale * v.y, 0.01f); }
                else if (bias) { v.x += bias[c]; v.y += bias[c + 1]; }
                *(float2*)&Cb[(size_t)rB * ldc + c] = v;
            }
        }
    }
}

// ---------------- both layers at once: bl[i][h]=We@a_l[i,h], br[i][h]=We@a_r[i,h] ----------------
__global__ void k_vecs2(const float* __restrict__ We,
                        const float* __restrict__ al, const float* __restrict__ ar) {
    int i = blockIdx.x;             // layer
    int t = threadIdx.x;
    int h = t >> 6, k = t & 63;
    float sl = 0.f, sr = 0.f;
    #pragma unroll 8
    for (int d = 0; d < 64; d++) {
        float w = We[k * 64 + d];
        sl += w * al[i * 256 + h * 64 + d];
        sr += w * ar[i * 256 + h * 64 + d];
    }
    g_bl[i * 256 + h * 64 + k] = sl;
    g_br[i * 256 + h * 64 + k] = sr;
}

// ---------------- prep: fp16 pack of cur (x-word only) + el/er dots. warp per node ----------------
__global__ __launch_bounds__(256) void k_prep(const float* __restrict__ cur, int lda, int layer) {
    __shared__ float blS[256], brS[256];
    int tid = threadIdx.x;
    blS[tid] = g_bl[layer * 256 + tid];
    brS[tid] = g_br[layer * 256 + tid];
    __syncthreads();
    int w = tid >> 5, lane = tid & 31;
    int n = blockIdx.x * 8 + w;
    float2 c = *(const float2*)&cur[(size_t)n * lda + lane * 2];
    __half2 ch = __floats2half2_rn(c.x, c.y);
    ((uint32_t*)&g_h2[n * 32 + lane])[0] = *(uint32_t*)&ch;   // .y (pooled) written by GEMM mode 2
    float p[8];
    #pragma unroll
    for (int h = 0; h < 4; h++) {
        p[h]     = c.x * blS[h * 64 + 2 * lane] + c.y * blS[h * 64 + 2 * lane + 1];
        p[4 + h] = c.x * brS[h * 64 + 2 * lane] + c.y * brS[h * 64 + 2 * lane + 1];
    }
    #pragma unroll
    for (int o = 16; o; o >>= 1) {
        #pragma unroll
        for (int q = 0; q < 8; q++) p[q] += __shfl_xor_sync(0xffffffffu, p[q], o);
    }
    if (lane == 0) {
        ((float4*)g_el)[n] = make_float4(p[0], p[1], p[2], p[3]);
        ((float4*)g_er)[n] = make_float4(p[4], p[5], p[6], p[7]);
    }
}

// ---------------- fused per-dst softmax (no-max) + aggregation + GaAN gate (pre-applied) ----------------
// Warp per dst. Interleaved 8B gathers, scalar FMA accumulation (R13-proven plain loop). No atomics.
__global__ __launch_bounds__(256) void k_agg(const float* __restrict__ Wg,
                                             const float* __restrict__ bg) {
    __shared__ float  WgS[768];
    __shared__ int    ssh[8][32];
    __shared__ float4 wsh[8][32];
    int tid = threadIdx.x, w = tid >> 5, lane = tid & 31;
    #pragma unroll
    for (int i = 0; i < 3; i++) WgS[tid + 256 * i] = Wg[tid + 256 * i];
    __syncthreads();
    int d = blockIdx.x * 8 + w;
    int r0 = g_rowptr[d], r1 = g_rowptr[d + 1];
    float4 erv = ((const float4*)g_er)[d];

    float s0 = 0.f, s1 = 0.f, s2 = 0.f, s3 = 0.f;
    float2 a0 = {0, 0}, a1 = {0, 0}, a2 = {0, 0}, a3 = {0, 0}, am = {0, 0};
    float2 amx = {-1e30f, -1e30f};
    int l2 = lane * 2;
    for (int base = r0; base < r1; base += 32) {
        int cnt = min(32, r1 - base);
        if (lane < cnt) {
            int s = g_col[base + lane];
            float4 e = ((const float4*)g_el)[s];
            float4 wv;
            wv.x = __expf(lrelu(e.x + erv.x, 0.2f));
            wv.y = __expf(lrelu(e.y + erv.y, 0.2f));
            wv.z = __expf(lrelu(e.z + erv.z, 0.2f));
            wv.w = __expf(lrelu(e.w + erv.w, 0.2f));
            s0 += wv.x; s1 += wv.y; s2 += wv.z; s3 += wv.w;
            ssh[w][lane] = s;
            wsh[w][lane] = wv;
        }
        __syncwarp();
        for (int t = 0; t < cnt; t++) {
            int s = ssh[w][t];
            float4 wv = wsh[w][t];
            uint2 hv = __ldg(&g_h2[(size_t)s * 32 + lane]);
            float2 c  = __half22float2(*(__half2*)&hv.x);
            float2 pp = __half22float2(*(__half2*)&hv.y);
            a0.x += wv.x * c.x; a0.y += wv.x * c.y;
            a1.x += wv.y * c.x; a1.y += wv.y * c.y;
            a2.x += wv.z * c.x; a2.y += wv.z * c.y;
            a3.x += wv.w * c.x; a3.y += wv.w * c.y;
            am.x += c.x;        am.y += c.y;
            amx.x = fmaxf(amx.x, pp.x);
            amx.y = fmaxf(amx.y, pp.y);
        }
        __syncwarp();
    }
    #pragma unroll
    for (int o = 16; o; o >>= 1) {
        s0 += __shfl_xor_sync(0xffffffffu, s0, o);
        s1 += __shfl_xor_sync(0xffffffffu, s1, o);
        s2 += __shfl_xor_sync(0xffffffffu, s2, o);
        s3 += __shfl_xor_sync(0xffffffffu, s3, o);
    }
    float dinv = 1.f / (float)(r1 - r0);

    // GaAN gate: g = sigmoid([cur_d, mx, mn] @ Wg + bg)
    float2 cd = __half22float2(*(__half2*)&g_h2[(size_t)d * 32 + lane].x);
    float gin[6] = {cd.x, cd.y, amx.x, amx.y, am.x * dinv, am.y * dinv};
    int   kbase[3] = {l2, 64 + l2, 128 + l2};
    float gp0 = 0.f, gp1 = 0.f, gp2 = 0.f, gp3 = 0.f;
    #pragma unroll
    for (int q = 0; q < 3; q++) {
        #pragma unroll
        for (int e2 = 0; e2 < 2; e2++) {
            float v = gin[q * 2 + e2];
            float4 wr = *(const float4*)&WgS[(kbase[q] + e2) * 4];
            gp0 += v * wr.x; gp1 += v * wr.y; gp2 += v * wr.z; gp3 += v * wr.w;
        }
    }
    #pragma unroll
    for (int o = 16; o; o >>= 1) {
        gp0 += __shfl_xor_sync(0xffffffffu, gp0, o);
        gp1 += __shfl_xor_sync(0xffffffffu, gp1, o);
        gp2 += __shfl_xor_sync(0xffffffffu, gp2, o);
        gp3 += __shfl_xor_sync(0xffffffffu, gp3, o);
    }
    float g0 = 1.f / (1.f + __expf(-(gp0 + bg[0])));
    float g1 = 1.f / (1.f + __expf(-(gp1 + bg[1])));
    float g2 = 1.f / (1.f + __expf(-(gp2 + bg[2])));
    float g3 = 1.f / (1.f + __expf(-(gp3 + bg[3])));

    float i0 = g0 / s0, i1 = g1 / s1, i2 = g2 / s2, i3 = g3 / s3;
    float* ap = &g_acc[d * 256];
    *(float2*)&ap[l2]       = make_float2(a0.x * i0, a0.y * i0);
    *(float2*)&ap[64 + l2]  = make_float2(a1.x * i1, a1.y * i1);
    *(float2*)&ap[128 + l2] = make_float2(a2.x * i2, a2.y * i2);
    *(float2*)&ap[192 + l2] = make_float2(a3.x * i3, a3.y * i3);
}

// ---------------- launch ----------------
extern "C" void kernel_launch(void* const* d_in, const int* in_sizes, int n_in,
                              void* d_out, int out_size) {
    const float* ft    = (const float*)d_in[0];
    const float* Wp    = (const float*)d_in[1];
    const float* We    = (const float*)d_in[2];
    const float* a_l   = (const float*)d_in[3];
    const float* a_r   = (const float*)d_in[4];
    const float* Wv    = (const float*)d_in[5];
    const float* Wgp   = (const float*)d_in[6];
    const float* Wgate = (const float*)d_in[7];
    const float* bgate = (const float*)d_in[8];
    const float* Wtran = (const float*)d_in[9];
    const float* btran = (const float*)d_in[10];
    const int*   src   = (const int*)d_in[11];
    const int*   dst   = (const int*)d_in[12];
    int ne = in_sizes[11];
    float* out = (float*)d_out;

    float *p_hcat, *p_curA, *p_acc;
    uint2* p_bfrag;
    uint2* p_h2;
    cudaGetSymbolAddress((void**)&p_hcat, g_hcat);
    cudaGetSymbolAddress((void**)&p_curA, g_curA);
    cudaGetSymbolAddress((void**)&p_acc, g_acc);
    cudaGetSymbolAddress((void**)&p_bfrag, g_bfrag);
    cudaGetSymbolAddress((void**)&p_h2, g_h2);

    cudaFuncSetAttribute(k_mma<2>, cudaFuncAttributeMaxDynamicSharedMemorySize, MMA_SMEM);
    cudaFuncSetAttribute(k_mma<1>, cudaFuncAttributeMaxDynamicSharedMemorySize, MMA_SMEM);

    const int MB = (NN + 127) / 128;  // 391
    int eb = (ne + 255) / 256;

    // slots 1-3
    k_zero_deg<<<(NN + 255) / 256, 256>>>();
    k_deg<<<eb, 256>>>(dst, ne);
    k_splitAll<<<(FR_TOTAL / 2 + 255) / 256, 256>>>(Wp, Wgp, Wv, Wtran);
    // slot 4: proj GEMM (profiled launch), 1xTF32 -- proj_feat = ft @ Wp -> hcat[:,0:64)
    k_mma<1><<<dim3(MB, 1, 1), 256, MMA_SMEM>>>(ft, 512, 0, p_bfrag + FR_WP, 0, p_hcat, 320, 0, NN, 512, nullptr, 0, 1.f);
    // CSR + per-layer attention vectors
    k_scan1<<<SCB, 1024>>>();
    k_scan2<<<1, 64>>>();
    k_scan3<<<SCB, 1024>>>();
    k_fill<<<eb, 256>>>(src, dst, ne);
    k_vecs2<<<2, 256>>>(We, a_l, a_r);

    for (int i = 0; i < 2; i++) {
        const float* cur = i ? p_curA : p_hcat;
        int lda = i ? 64 : 320;
        // pooled = cur @ Wg_pool[i], written as fp16 straight into g_h2[..].y (mode 2, 1xTF32)
        k_mma<1><<<dim3(MB, 1, 1), 256, MMA_SMEM>>>(cur, lda, 0, p_bfrag + (i ? FR_WGP1 : FR_WGP0), 0,
                                                    (float*)p_h2, 0, 0, NN, 64, nullptr, 2, 1.f);
        k_prep<<<6250, 256>>>(cur, lda, i);
        k_agg<<<6250, 256>>>(Wgate + i * 768, bgate + i * 4);
        if (i == 0) {
            // cur1 = lrelu(0.25 * acc_gated @ Wv0_stacked[256,64])  (1xTF32)
            k_mma<1><<<dim3(MB, 1, 1), 256, MMA_SMEM>>>(p_acc, 256, 0, p_bfrag + FR_WV0, 0,
                                                        p_curA, 64, 0, NN, 256, nullptr, 1, 0.25f);
        } else {
            // hcat[:,64+h*64+:] = lrelu(acc_gated[:,h,:] @ Wv1_h)   (2xTF32, batched over heads)
            k_mma<2><<<dim3(MB, 1, 4), 256, MMA_SMEM>>>(p_acc, 256, 64, p_bfrag + FR_WV1, 2048,
                                                        p_hcat + 64, 320, 64, NN, 64, nullptr, 1, 1.f);
        }
    }

    // out = hcat[N,320] @ Wtran[320,64] + btran  (1xTF32)
    k_mma<1><<<dim3(MB, 1, 1), 256, MMA_SMEM>>>(p_hcat, 320, 0, p_bfrag + FR_WT, 0, out, 64, 0, NN, 320, btran, 0, 1.f);
}

// round 16
// speedup vs baseline: 1.0700x; 1.0047x over previous
#include <cuda_runtime.h>
#include <cuda_fp16.h>
#include <cstdint>

#define NN   50000
#define EEMAX 800000
#define HIDD 64
#define NH   4
#define SCB  ((NN + 1023) / 1024)   // 49 scan blocks

// frag-major B table offsets (uint2 units; stored pair-packed as uint4)
#define FR_WP    0
#define FR_WGP0  16384
#define FR_WGP1  18432
#define FR_WV0   20480
#define FR_WV1   28672
#define FR_WT    36864
#define FR_TOTAL 47104

// k_mma dynamic smem: double-buffered A (2*128*36 floats) + B (2*1024 uint2)
#define MMA_SMEM (2 * 128 * 36 * 4 + 2 * 1024 * 8)

// ---------------- scratch (device globals; no allocations allowed) ----------------
__device__ int   g_deg[NN];
__device__ int   g_rowptr[NN + 1];
__device__ int   g_cursor[NN];
__device__ int   g_part[64];
__device__ int   g_col[EEMAX];
__device__ __align__(16) uint2 g_bfrag[FR_TOTAL];
__device__ __align__(16) float g_hcat[NN * 320];    // [n][0:64)=proj, [64:320)=layer1 gated heads
__device__ __align__(16) float g_curA[NN * HIDD];
__device__ __align__(16) float g_el[NN * NH];
__device__ __align__(16) float g_er[NN * NH];
__device__ __align__(16) float g_acc[NN * NH * HIDD];
__device__ __align__(16) uint2 g_h2[NN * 32];       // [n][lane] = {cur half2, pooled half2}
__device__ float g_bl[2 * NH * HIDD];               // both layers
__device__ float g_br[2 * NH * HIDD];

__device__ __forceinline__ float lrelu(float x, float s) { return x > 0.f ? x : s * x; }

// ---------------- tf32 helpers ----------------
__device__ __forceinline__ void split_tf32(float x, uint32_t& hi, uint32_t& lo) {
    asm("cvt.rna.tf32.f32 %0, %1;" : "=r"(hi) : "f"(x));
    float r = x - __uint_as_float(hi);
    asm("cvt.rna.tf32.f32 %0, %1;" : "=r"(lo) : "f"(r));
}

__device__ __forceinline__ uint32_t to_tf32(float x) {
    uint32_t h;
    asm("cvt.rna.tf32.f32 %0, %1;" : "=r"(h) : "f"(x));
    return h;
}

__device__ __forceinline__ void mma8(float* d,
                                     uint32_t a0, uint32_t a1, uint32_t a2, uint32_t a3,
                                     uint32_t b0, uint32_t b1) {
    asm volatile(
        "mma.sync.aligned.m16n8k8.row.col.f32.tf32.tf32.f32 "
        "{%0,%1,%2,%3},{%4,%5,%6,%7},{%8,%9},{%0,%1,%2,%3};"
        : "+f"(d[0]), "+f"(d[1]), "+f"(d[2]), "+f"(d[3])
        : "r"(a0), "r"(a1), "r"(a2), "r"(a3), "r"(b0), "r"(b1));
}

// ---------------- CSR build ----------------
__global__ void k_zero_deg() {
    int i = blockIdx.x * blockDim.x + threadIdx.x;
    if (i < NN) g_deg[i] = 0;
}

__global__ void k_deg(const int* __restrict__ dst, int ne) {
    int e = blockIdx.x * blockDim.x + threadIdx.x;
    if (e < ne) atomicAdd(&g_deg[dst[e]], 1);
}

__global__ __launch_bounds__(1024) void k_scan1() {
    __shared__ int sh[32];
    int tid = threadIdx.x, lane = tid & 31, wid = tid >> 5;
    int i = blockIdx.x * 1024 + tid;
    int v = (i < NN) ? g_deg[i] : 0;
    #pragma unroll
    for (int o = 16; o; o >>= 1) v += __shfl_xor_sync(0xffffffffu, v, o);
    if (lane == 0) sh[wid] = v;
    __syncthreads();
    if (tid < 32) {
        int t = sh[tid];
        #pragma unroll
        for (int o = 16; o; o >>= 1) t += __shfl_xor_sync(0xffffffffu, t, o);
        if (tid == 0) g_part[blockIdx.x] = t;
    }
}

__global__ void k_scan2() {
    __shared__ int sh[64];
    int tid = threadIdx.x;
    int v = (tid < SCB) ? g_part[tid] : 0;
    sh[tid] = v;
    __syncthreads();
    #pragma unroll
    for (int off = 1; off < 64; off <<= 1) {
        int t = (tid >= off) ? sh[tid - off] : 0;
        __syncthreads();
        sh[tid] += t;
        __syncthreads();
    }
    if (tid < SCB) g_part[tid] = sh[tid] - v;
    if (tid == SCB - 1) g_rowptr[NN] = sh[tid];
}

__global__ __launch_bounds__(1024) void k_scan3() {
    __shared__ int sh[1024];
    int tid = threadIdx.x;
    int i = blockIdx.x * 1024 + tid;
    int v = (i < NN) ? g_deg[i] : 0;
    sh[tid] = v;
    __syncthreads();
    #pragma unroll
    for (int off = 1; off < 1024; off <<= 1) {
        int t = (tid >= off) ? sh[tid - off] : 0;
        __syncthreads();
        sh[tid] += t;
        __syncthreads();
    }
    if (i < NN) {
        int excl = sh[tid] - v + g_part[blockIdx.x];
        g_rowptr[i] = excl;
        g_cursor[i] = excl;
    }
}

__global__ void k_fill(const int* __restrict__ src, const int* __restrict__ dst, int ne) {
    int e = blockIdx.x * blockDim.x + threadIdx.x;
    if (e < ne) {
        int p = atomicAdd(&g_cursor[dst[e]], 1);
        g_col[p] = src[e];
    }
}

// ---------------- one-time: convert weights into PAIR-PACKED frag-major tf32-hi table ----------------
__global__ void k_splitAll(const float* __restrict__ Wp, const float* __restrict__ Wgp,
                           const float* __restrict__ Wv, const float* __restrict__ Wt) {
    int v4 = blockIdx.x * 256 + threadIdx.x;       // uint4 index, [0, FR_TOTAL/2)
    if (v4 >= FR_TOTAL / 2) return;
    int u = v4 * 2;
    const float* src; int off;
    if (u < FR_WGP0)      { src = Wp;         off = FR_WP;   }
    else if (u < FR_WGP1) { src = Wgp;        off = FR_WGP0; }
    else if (u < FR_WV0)  { src = Wgp + 4096; off = FR_WGP1; }
    else if (u < FR_WV1)  { src = Wv;         off = FR_WV0;  }
    else if (u < FR_WT)   { src = Wv + 16384; off = FR_WV1;  }
    else                  { src = Wt;         off = FR_WT;   }
    int local = v4 - off / 2;
    int k8 = local >> 7, rem = local & 127;
    int np = rem >> 5, lane = rem & 31;
    int g = lane >> 2, t4 = lane & 3;
    int col0 = (2 * np) * 8 + g, col1 = (2 * np + 1) * 8 + g;
    float v00 = src[(k8 * 8 + t4) * 64 + col0];
    float v01 = src[(k8 * 8 + t4 + 4) * 64 + col0];
    float v10 = src[(k8 * 8 + t4) * 64 + col1];
    float v11 = src[(k8 * 8 + t4 + 4) * 64 + col1];
    ((uint4*)g_bfrag)[v4] = make_uint4(to_tf32(v00), to_tf32(v01), to_tf32(v10), to_tf32(v11));
}

// ---------------- tensor-core GEMM: C[M,64] = f(A[M,K] @ B[K,64]) ----------------
// PASSES=2: (ah+al)*bh; PASSES=1: ah*bh only.
// mode 0: C = v (+bias); mode 1: C = lrelu(scale*v); mode 2: g_h2[..].y = half2(v) (pooled path)
template <int PASSES>
__global__ __launch_bounds__(256, 3) void k_mma(
    const float* __restrict__ A, int lda, int aBS,
    const uint2* __restrict__ Bf, int bFS,
    float* __restrict__ C, int ldc, int cBS,
    int M, int K, const float* __restrict__ bias, int mode, float scale)
{
    extern __shared__ char smem_raw[];
    float (*As)[128][36] = reinterpret_cast<float(*)[128][36]>(smem_raw);
    uint2* Bs = reinterpret_cast<uint2*>(smem_raw + 2 * 128 * 36 * 4);
    const float* Ab  = A  + (size_t)blockIdx.z * aBS;
    const uint2* Bfb = Bf + (size_t)blockIdx.z * bFS;
    float*       Cb  = C  + (size_t)blockIdx.z * cBS;
    int row0 = blockIdx.x * 128;
    int tid = threadIdx.x, w = tid >> 5, lane = tid & 31;
    int g = lane >> 2, t4 = lane & 3;
    int sk = (tid & 7) * 4, srr = tid >> 3;

    float d[8][4];
    #pragma unroll
    for (int i = 0; i < 8; i++)
        #pragma unroll
        for (int j = 0; j < 4; j++) d[i][j] = 0.f;

    auto stage = [&](int buf, int kk) {
        #pragma unroll
        for (int p = 0; p < 4; p++) {
            int r = p * 32 + srr;
            int gr = row0 + r;
            uint32_t sa = (uint32_t)__cvta_generic_to_shared(&As[buf][r][sk]);
            const float* gp = Ab + (size_t)gr * lda + kk + sk;
            int sz = (gr < M) ? 16 : 0;
            asm volatile("cp.async.cg.shared.global [%0], [%1], 16, %2;\n"
                         :: "r"(sa), "l"(gp), "r"(sz));
        }
        const uint2* bsrc = Bfb + (size_t)(kk >> 3) * 256 + tid;
        #pragma unroll
        for (int j = 0; j < 4; j++) {
            uint32_t sa = (uint32_t)__cvta_generic_to_shared(&Bs[buf * 1024 + tid + 256 * j]);
            asm volatile("cp.async.ca.shared.global [%0], [%1], 8;\n"
                         :: "r"(sa), "l"(bsrc + 256 * j));
        }
        asm volatile("cp.async.commit_group;\n");
    };

    stage(0, 0);
    int buf = 0;
    for (int kk = 0; kk < K; kk += 32) {
        if (kk + 32 < K) {
            stage(buf ^ 1, kk + 32);
            asm volatile("cp.async.wait_group 1;\n");
        } else {
            asm volatile("cp.async.wait_group 0;\n");
        }
        __syncthreads();

        const uint4* Bs4 = (const uint4*)(Bs + buf * 1024);
        #pragma unroll
        for (int k8 = 0; k8 < 4; k8++) {
            int kb = k8 * 8;
            float a0 = As[buf][w * 16 + g][kb + t4];
            float a1 = As[buf][w * 16 + g + 8][kb + t4];
            float a2 = As[buf][w * 16 + g][kb + t4 + 4];
            float a3 = As[buf][w * 16 + g + 8][kb + t4 + 4];
            uint32_t ah0, al0, ah1, al1, ah2, al2, ah3, al3;
            if (PASSES == 2) {
                split_tf32(a0, ah0, al0);
                split_tf32(a1, ah1, al1);
                split_tf32(a2, ah2, al2);
                split_tf32(a3, ah3, al3);
            } else {
                ah0 = to_tf32(a0); ah1 = to_tf32(a1);
                ah2 = to_tf32(a2); ah3 = to_tf32(a3);
            }
            #pragma unroll
            for (int np = 0; np < 4; np++) {
                uint4 bb = Bs4[(k8 * 4 + np) * 32 + lane];
                if (PASSES == 2) {
                    mma8(d[2 * np],     al0, al1, al2, al3, bb.x, bb.y);
                    mma8(d[2 * np + 1], al0, al1, al2, al3, bb.z, bb.w);
                }
                mma8(d[2 * np],     ah0, ah1, ah2, ah3, bb.x, bb.y);
                mma8(d[2 * np + 1], ah0, ah1, ah2, ah3, bb.z, bb.w);
            }
        }
        __syncthreads();   // protect buf before it is re-staged next iteration
        buf ^= 1;
    }

    int rb = row0 + w * 16;
    int rA = rb + g, rB = rb + g + 8;
    #pragma unroll
    for (int nt = 0; nt < 8; nt++) {
        int c = nt * 8 + t4 * 2;
        if (rA < M) {
            float2 v = make_float2(d[nt][0], d[nt][1]);
            if (mode == 2) {
                __half2 hh = __floats2half2_rn(v.x, v.y);
                ((uint32_t*)Cb)[((size_t)rA * 32 + (c >> 1)) * 2 + 1] = *(uint32_t*)&hh;
            } else {
                if (mode == 1) { v.x = lrelu(scale * v.x, 0.01f); v.y = lrelu(scale * v.y, 0.01f); }
                else if (bias) { v.x += bias[c]; v.y += bias[c + 1]; }
                *(float2*)&Cb[(size_t)rA * ldc + c] = v;
            }
        }
        if (rB < M) {
            float2 v = make_float2(d[nt][2], d[nt][3]);
            if (mode == 2) {
                __half2 hh = __floats2half2_rn(v.x, v.y);
                ((uint32_t*)Cb)[((size_t)rB * 32 + (c >> 1)) * 2 + 1] = *(uint32_t*)&hh;
            } else {
                if (mode == 1) { v.x = lrelu(scale * v.x, 0.01f); v.y = lrelu(scale * v.y, 0.01f); }
                else if (bias) { v.x += bias[c]; v.y += bias[c + 1]; }
                *(float2*)&Cb[(size_t)rB * ldc + c] = v;
            }
        }
    }
}

// ---------------- both layers at once: bl[i][h]=We@a_l[i,h], br[i][h]=We@a_r[i,h] ----------------
__global__ void k_vecs2(const float* __restrict__ We,
                        const float* __restrict__ al, const float* __restrict__ ar) {
    int i = blockIdx.x;             // layer
    int t = threadIdx.x;
    int h = t >> 6, k = t & 63;
    float sl = 0.f, sr = 0.f;
    #pragma unroll 8
    for (int d = 0; d < 64; d++) {
        float w = We[k * 64 + d];
        sl += w * al[i * 256 + h * 64 + d];
        sr += w * ar[i * 256 + h * 64 + d];
    }
    g_bl[i * 256 + h * 64 + k] = sl;
    g_br[i * 256 + h * 64 + k] = sr;
}

// ---------------- prep: fp16 pack of cur (x-word only) + el/er dots. warp per node ----------------
__global__ __launch_bounds__(256) void k_prep(const float* __restrict__ cur, int lda, int layer) {
    __shared__ float blS[256], brS[256];
    int tid = threadIdx.x;
    blS[tid] = g_bl[layer * 256 + tid];
    brS[tid] = g_br[layer * 256 + tid];
    __syncthreads();
    int w = tid >> 5, lane = tid & 31;
    int n = blockIdx.x * 8 + w;
    float2 c = *(const float2*)&cur[(size_t)n * lda + lane * 2];
    __half2 ch = __floats2half2_rn(c.x, c.y);
    ((uint32_t*)&g_h2[n * 32 + lane])[0] = *(uint32_t*)&ch;   // .y (pooled) written by GEMM mode 2
    float p[8];
    #pragma unroll
    for (int h = 0; h < 4; h++) {
        p[h]     = c.x * blS[h * 64 + 2 * lane] + c.y * blS[h * 64 + 2 * lane + 1];
        p[4 + h] = c.x * brS[h * 64 + 2 * lane] + c.y * brS[h * 64 + 2 * lane + 1];
    }
    #pragma unroll
    for (int o = 16; o; o >>= 1) {
        #pragma unroll
        for (int q = 0; q < 8; q++) p[q] += __shfl_xor_sync(0xffffffffu, p[q], o);
    }
    if (lane == 0) {
        ((float4*)g_el)[n] = make_float4(p[0], p[1], p[2], p[3]);
        ((float4*)g_er)[n] = make_float4(p[4], p[5], p[6], p[7]);
    }
}

// ---------------- fused per-dst softmax (no-max) + aggregation + GaAN gate (pre-applied) ----------------
// Warp per dst. 2-wide batched 8B gathers (genuine MLP=2), scalar FMA accumulation. No atomics.
__global__ __launch_bounds__(256) void k_agg(const float* __restrict__ Wg,
                                             const float* __restrict__ bg) {
    __shared__ float  WgS[768];
    __shared__ int    ssh[8][32];
    __shared__ float4 wsh[8][32];
    int tid = threadIdx.x, w = tid >> 5, lane = tid & 31;
    #pragma unroll
    for (int i = 0; i < 3; i++) WgS[tid + 256 * i] = Wg[tid + 256 * i];
    __syncthreads();
    int d = blockIdx.x * 8 + w;
    int r0 = g_rowptr[d], r1 = g_rowptr[d + 1];
    float4 erv = ((const float4*)g_er)[d];

    float s0 = 0.f, s1 = 0.f, s2 = 0.f, s3 = 0.f;
    float2 a0 = {0, 0}, a1 = {0, 0}, a2 = {0, 0}, a3 = {0, 0}, am = {0, 0};
    float2 amx = {-1e30f, -1e30f};
    int l2 = lane * 2;
    for (int base = r0; base < r1; base += 32) {
        int cnt = min(32, r1 - base);
        if (lane < cnt) {
            int s = g_col[base + lane];
            float4 e = ((const float4*)g_el)[s];
            float4 wv;
            wv.x = __expf(lrelu(e.x + erv.x, 0.2f));
            wv.y = __expf(lrelu(e.y + erv.y, 0.2f));
            wv.z = __expf(lrelu(e.z + erv.z, 0.2f));
            wv.w = __expf(lrelu(e.w + erv.w, 0.2f));
            s0 += wv.x; s1 += wv.y; s2 += wv.z; s3 += wv.w;
            ssh[w][lane] = s;
            wsh[w][lane] = wv;
        }
        __syncwarp();
        int t = 0;
        for (; t + 1 < cnt; t += 2) {
            int sa = ssh[w][t], sb = ssh[w][t + 1];
            uint2 hva = __ldg(&g_h2[(size_t)sa * 32 + lane]);   // both loads issue
            uint2 hvb = __ldg(&g_h2[(size_t)sb * 32 + lane]);   // back-to-back: MLP=2
            float4 wva = wsh[w][t];
            float4 wvb = wsh[w][t + 1];
            float2 ca  = __half22float2(*(__half2*)&hva.x);
            float2 ppa = __half22float2(*(__half2*)&hva.y);
            a0.x += wva.x * ca.x; a0.y += wva.x * ca.y;
            a1.x += wva.y * ca.x; a1.y += wva.y * ca.y;
            a2.x += wva.z * ca.x; a2.y += wva.z * ca.y;
            a3.x += wva.w * ca.x; a3.y += wva.w * ca.y;
            am.x += ca.x;         am.y += ca.y;
            amx.x = fmaxf(amx.x, ppa.x);
            amx.y = fmaxf(amx.y, ppa.y);
            float2 cb  = __half22float2(*(__half2*)&hvb.x);
            float2 ppb = __half22float2(*(__half2*)&hvb.y);
            a0.x += wvb.x * cb.x; a0.y += wvb.x * cb.y;
            a1.x += wvb.y * cb.x; a1.y += wvb.y * cb.y;
            a2.x += wvb.z * cb.x; a2.y += wvb.z * cb.y;
            a3.x += wvb.w * cb.x; a3.y += wvb.w * cb.y;
            am.x += cb.x;         am.y += cb.y;
            amx.x = fmaxf(amx.x, ppb.x);
            amx.y = fmaxf(amx.y, ppb.y);
        }
        if (t < cnt) {
            int s = ssh[w][t];
            float4 wv = wsh[w][t];
            uint2 hv = __ldg(&g_h2[(size_t)s * 32 + lane]);
            float2 c  = __half22float2(*(__half2*)&hv.x);
            float2 pp = __half22float2(*(__half2*)&hv.y);
            a0.x += wv.x * c.x; a0.y += wv.x * c.y;
            a1.x += wv.y * c.x; a1.y += wv.y * c.y;
            a2.x += wv.z * c.x; a2.y += wv.z * c.y;
            a3.x += wv.w * c.x; a3.y += wv.w * c.y;
            am.x += c.x;        am.y += c.y;
            amx.x = fmaxf(amx.x, pp.x);
            amx.y = fmaxf(amx.y, pp.y);
        }
        __syncwarp();
    }
    #pragma unroll
    for (int o = 16; o; o >>= 1) {
        s0 += __shfl_xor_sync(0xffffffffu, s0, o);
        s1 += __shfl_xor_sync(0xffffffffu, s1, o);
        s2 += __shfl_xor_sync(0xffffffffu, s2, o);
        s3 += __shfl_xor_sync(0xffffffffu, s3, o);
    }
    float dinv = 1.f / (float)(r1 - r0);

    // GaAN gate: g = sigmoid([cur_d, mx, mn] @ Wg + bg)
    float2 cd = __half22float2(*(__half2*)&g_h2[(size_t)d * 32 + lane].x);
    float gin[6] = {cd.x, cd.y, amx.x, amx.y, am.x * dinv, am.y * dinv};
    int   kbase[3] = {l2, 64 + l2, 128 + l2};
    float gp0 = 0.f, gp1 = 0.f, gp2 = 0.f, gp3 = 0.f;
    #pragma unroll
    for (int q = 0; q < 3; q++) {
        #pragma unroll
        for (int e2 = 0; e2 < 2; e2++) {
            float v = gin[q * 2 + e2];
            float4 wr = *(const float4*)&WgS[(kbase[q] + e2) * 4];
            gp0 += v * wr.x; gp1 += v * wr.y; gp2 += v * wr.z; gp3 += v * wr.w;
        }
    }
    #pragma unroll
    for (int o = 16; o; o >>= 1) {
        gp0 += __shfl_xor_sync(0xffffffffu, gp0, o);
        gp1 += __shfl_xor_sync(0xffffffffu, gp1, o);
        gp2 += __shfl_xor_sync(0xffffffffu, gp2, o);
        gp3 += __shfl_xor_sync(0xffffffffu, gp3, o);
    }
    float g0 = 1.f / (1.f + __expf(-(gp0 + bg[0])));
    float g1 = 1.f / (1.f + __expf(-(gp1 + bg[1])));
    float g2 = 1.f / (1.f + __expf(-(gp2 + bg[2])));
    float g3 = 1.f / (1.f + __expf(-(gp3 + bg[3])));

    float i0 = g0 / s0, i1 = g1 / s1, i2 = g2 / s2, i3 = g3 / s3;
    float* ap = &g_acc[d * 256];
    *(float2*)&ap[l2]       = make_float2(a0.x * i0, a0.y * i0);
    *(float2*)&ap[64 + l2]  = make_float2(a1.x * i1, a1.y * i1);
    *(float2*)&ap[128 + l2] = make_float2(a2.x * i2, a2.y * i2);
    *(float2*)&ap[192 + l2] = make_float2(a3.x * i3, a3.y * i3);
}

// ---------------- launch ----------------
extern "C" void kernel_launch(void* const* d_in, const int* in_sizes, int n_in,
                              void* d_out, int out_size) {
    const float* ft    = (const float*)d_in[0];
    const float* Wp    = (const float*)d_in[1];
    const float* We    = (const float*)d_in[2];
    const float* a_l   = (const float*)d_in[3];
    const float* a_r   = (const float*)d_in[4];
    const float* Wv    = (const float*)d_in[5];
    const float* Wgp   = (const float*)d_in[6];
    const float* Wgate = (const float*)d_in[7];
    const float* bgate = (const float*)d_in[8];
    const float* Wtran = (const float*)d_in[9];
    const float* btran = (const float*)d_in[10];
    const int*   src   = (const int*)d_in[11];
    const int*   dst   = (const int*)d_in[12];
    int ne = in_sizes[11];
    float* out = (float*)d_out;

    float *p_hcat, *p_curA, *p_acc;
    uint2* p_bfrag;
    uint2* p_h2;
    cudaGetSymbolAddress((void**)&p_hcat, g_hcat);
    cudaGetSymbolAddress((void**)&p_curA, g_curA);
    cudaGetSymbolAddress((void**)&p_acc, g_acc);
    cudaGetSymbolAddress((void**)&p_bfrag, g_bfrag);
    cudaGetSymbolAddress((void**)&p_h2, g_h2);

    cudaFuncSetAttribute(k_mma<2>, cudaFuncAttributeMaxDynamicSharedMemorySize, MMA_SMEM);
    cudaFuncSetAttribute(k_mma<1>, cudaFuncAttributeMaxDynamicSharedMemorySize, MMA_SMEM);

    const int MB = (NN + 127) / 128;  // 391
    int eb = (ne + 255) / 256;

    // slots 1-3
    k_zero_deg<<<(NN + 255) / 256, 256>>>();
    k_deg<<<eb, 256>>>(dst, ne);
    k_splitAll<<<(FR_TOTAL / 2 + 255) / 256, 256>>>(Wp, Wgp, Wv, Wtran);
    // slot 4: proj GEMM (profiled launch), 1xTF32 -- proj_feat = ft @ Wp -> hcat[:,0:64)
    k_mma<1><<<dim3(MB, 1, 1), 256, MMA_SMEM>>>(ft, 512, 0, p_bfrag + FR_WP, 0, p_hcat, 320, 0, NN, 512, nullptr, 0, 1.f);
    // CSR + per-layer attention vectors
    k_scan1<<<SCB, 1024>>>();
    k_scan2<<<1, 64>>>();
    k_scan3<<<SCB, 1024>>>();
    k_fill<<<eb, 256>>>(src, dst, ne);
    k_vecs2<<<2, 256>>>(We, a_l, a_r);

    for (int i = 0; i < 2; i++) {
        const float* cur = i ? p_curA : p_hcat;
        int lda = i ? 64 : 320;
        // pooled = cur @ Wg_pool[i], written as fp16 straight into g_h2[..].y (mode 2, 1xTF32)
        k_mma<1><<<dim3(MB, 1, 1), 256, MMA_SMEM>>>(cur, lda, 0, p_bfrag + (i ? FR_WGP1 : FR_WGP0), 0,
                                                    (float*)p_h2, 0, 0, NN, 64, nullptr, 2, 1.f);
        k_prep<<<6250, 256>>>(cur, lda, i);
        k_agg<<<6250, 256>>>(Wgate + i * 768, bgate + i * 4);
        if (i == 0) {
            // cur1 = lrelu(0.25 * acc_gated @ Wv0_stacked[256,64])  (1xTF32)
            k_mma<1><<<dim3(MB, 1, 1), 256, MMA_SMEM>>>(p_acc, 256, 0, p_bfrag + FR_WV0, 0,
                                                        p_curA, 64, 0, NN, 256, nullptr, 1, 0.25f);
        } else {
            // hcat[:,64+h*64+:] = lrelu(acc_gated[:,h,:] @ Wv1_h)   (1xTF32, batched over heads)
            k_mma<1><<<dim3(MB, 1, 4), 256, MMA_SMEM>>>(p_acc, 256, 64, p_bfrag + FR_WV1, 2048,
                                                        p_hcat + 64, 320, 64, NN, 64, nullptr, 1, 1.f);
        }
    }

    // out = hcat[N,320] @ Wtran[320,64] + btran  (1xTF32)
    k_mma<1><<<dim3(MB, 1, 1), 256, MMA_SMEM>>>(p_hcat, 320, 0, p_bfrag + FR_WT, 0, out, 64, 0, NN, 320, btran, 0, 1.f);
}

// round 17
// speedup vs baseline: 1.1692x; 1.0927x over previous
#include <cuda_runtime.h>
#include <cuda_fp16.h>
#include <cstdint>

#define NN   50000
#define EEMAX 800000
#define HIDD 64
#define NH   4
#define SCB  ((NN + 1023) / 1024)   // 49 scan blocks

// frag-major B table offsets (uint2 units; stored pair-packed as uint4)
#define FR_WP    0
#define FR_WGP0  16384
#define FR_WGP1  18432
#define FR_WV0   20480
#define FR_WV1   28672
#define FR_WT    36864
#define FR_TOTAL 47104

// k_mma dynamic smem: double-buffered A (2*128*36 floats) + B (2*1024 uint2)
#define MMA_SMEM (2 * 128 * 36 * 4 + 2 * 1024 * 8)

// ---------------- scratch (device globals; no allocations allowed) ----------------
__device__ int   g_deg[NN];
__device__ int   g_rowptr[NN + 1];
__device__ int   g_cursor[NN];
__device__ int   g_part[64];
__device__ int   g_col[EEMAX];
__device__ __align__(16) uint2 g_bfrag[FR_TOTAL];
__device__ __align__(16) float g_hcat[NN * 320];    // [n][0:64)=proj, [64:320)=layer1 gated heads
__device__ __align__(16) float g_curA[NN * HIDD];
__device__ __align__(16) float g_el[NN * NH];
__device__ __align__(16) float g_er[NN * NH];
__device__ __align__(16) float g_acc[NN * NH * HIDD];
__device__ __align__(16) uint2 g_h2[NN * 32];       // [n][lane] = {cur half2, pooled half2}
__device__ float g_bl[2 * NH * HIDD];               // both layers
__device__ float g_br[2 * NH * HIDD];

__device__ __forceinline__ float lrelu(float x, float s) { return x > 0.f ? x : s * x; }

// ---------------- tf32 helpers ----------------
__device__ __forceinline__ void split_tf32(float x, uint32_t& hi, uint32_t& lo) {
    asm("cvt.rna.tf32.f32 %0, %1;" : "=r"(hi) : "f"(x));
    float r = x - __uint_as_float(hi);
    asm("cvt.rna.tf32.f32 %0, %1;" : "=r"(lo) : "f"(r));
}

__device__ __forceinline__ uint32_t to_tf32(float x) {
    uint32_t h;
    asm("cvt.rna.tf32.f32 %0, %1;" : "=r"(h) : "f"(x));
    return h;
}

__device__ __forceinline__ void mma8(float* d,
                                     uint32_t a0, uint32_t a1, uint32_t a2, uint32_t a3,
                                     uint32_t b0, uint32_t b1) {
    asm volatile(
        "mma.sync.aligned.m16n8k8.row.col.f32.tf32.tf32.f32 "
        "{%0,%1,%2,%3},{%4,%5,%6,%7},{%8,%9},{%0,%1,%2,%3};"
        : "+f"(d[0]), "+f"(d[1]), "+f"(d[2]), "+f"(d[3])
        : "r"(a0), "r"(a1), "r"(a2), "r"(a3), "r"(b0), "r"(b1));
}

// ---------------- CSR build ----------------
__global__ void k_zero_deg() {
    int i = blockIdx.x * blockDim.x + threadIdx.x;
    if (i < NN) g_deg[i] = 0;
}

__global__ void k_deg(const int* __restrict__ dst, int ne) {
    int e = blockIdx.x * blockDim.x + threadIdx.x;
    if (e < ne) atomicAdd(&g_deg[dst[e]], 1);
}

__global__ __launch_bounds__(1024) void k_scan1() {
    __shared__ int sh[32];
    int tid = threadIdx.x, lane = tid & 31, wid = tid >> 5;
    int i = blockIdx.x * 1024 + tid;
    int v = (i < NN) ? g_deg[i] : 0;
    #pragma unroll
    for (int o = 16; o; o >>= 1) v += __shfl_xor_sync(0xffffffffu, v, o);
    if (lane == 0) sh[wid] = v;
    __syncthreads();
    if (tid < 32) {
        int t = sh[tid];
        #pragma unroll
        for (int o = 16; o; o >>= 1) t += __shfl_xor_sync(0xffffffffu, t, o);
        if (tid == 0) g_part[blockIdx.x] = t;
    }
}

__global__ void k_scan2() {
    __shared__ int sh[64];
    int tid = threadIdx.x;
    int v = (tid < SCB) ? g_part[tid] : 0;
    sh[tid] = v;
    __syncthreads();
    #pragma unroll
    for (int off = 1; off < 64; off <<= 1) {
        int t = (tid >= off) ? sh[tid - off] : 0;
        __syncthreads();
        sh[tid] += t;
        __syncthreads();
    }
    if (tid < SCB) g_part[tid] = sh[tid] - v;
    if (tid == SCB - 1) g_rowptr[NN] = sh[tid];
}

__global__ __launch_bounds__(1024) void k_scan3() {
    __shared__ int sh[1024];
    int tid = threadIdx.x;
    int i = blockIdx.x * 1024 + tid;
    int v = (i < NN) ? g_deg[i] : 0;
    sh[tid] = v;
    __syncthreads();
    #pragma unroll
    for (int off = 1; off < 1024; off <<= 1) {
        int t = (tid >= off) ? sh[tid - off] : 0;
        __syncthreads();
        sh[tid] += t;
        __syncthreads();
    }
    if (i < NN) {
        int excl = sh[tid] - v + g_part[blockIdx.x];
        g_rowptr[i] = excl;
        g_cursor[i] = excl;
    }
}

__global__ void k_fill(const int* __restrict__ src, const int* __restrict__ dst, int ne) {
    int e = blockIdx.x * blockDim.x + threadIdx.x;
    if (e < ne) {
        int p = atomicAdd(&g_cursor[dst[e]], 1);
        g_col[p] = src[e];
    }
}

// ---------------- one-time: convert weights into PAIR-PACKED frag-major tf32-hi table ----------------
__global__ void k_splitAll(const float* __restrict__ Wp, const float* __restrict__ Wgp,
                           const float* __restrict__ Wv, const float* __restrict__ Wt) {
    int v4 = blockIdx.x * 256 + threadIdx.x;       // uint4 index, [0, FR_TOTAL/2)
    if (v4 >= FR_TOTAL / 2) return;
    int u = v4 * 2;
    const float* src; int off;
    if (u < FR_WGP0)      { src = Wp;         off = FR_WP;   }
    else if (u < FR_WGP1) { src = Wgp;        off = FR_WGP0; }
    else if (u < FR_WV0)  { src = Wgp + 4096; off = FR_WGP1; }
    else if (u < FR_WV1)  { src = Wv;         off = FR_WV0;  }
    else if (u < FR_WT)   { src = Wv + 16384; off = FR_WV1;  }
    else                  { src = Wt;         off = FR_WT;   }
    int local = v4 - off / 2;
    int k8 = local >> 7, rem = local & 127;
    int np = rem >> 5, lane = rem & 31;
    int g = lane >> 2, t4 = lane & 3;
    int col0 = (2 * np) * 8 + g, col1 = (2 * np + 1) * 8 + g;
    float v00 = src[(k8 * 8 + t4) * 64 + col0];
    float v01 = src[(k8 * 8 + t4 + 4) * 64 + col0];
    float v10 = src[(k8 * 8 + t4) * 64 + col1];
    float v11 = src[(k8 * 8 + t4 + 4) * 64 + col1];
    ((uint4*)g_bfrag)[v4] = make_uint4(to_tf32(v00), to_tf32(v01), to_tf32(v10), to_tf32(v11));
}

// ---------------- tensor-core GEMM: C[M,64] = f(A[M,K] @ B[K,64]) ----------------
// PASSES=2: (ah+al)*bh; PASSES=1: ah*bh only.
// mode 0: C = v (+bias); mode 1: C = lrelu(scale*v); mode 2: g_h2[..].y = half2(v) (pooled path)
template <int PASSES>
__global__ __launch_bounds__(256, 3) void k_mma(
    const float* __restrict__ A, int lda, int aBS,
    const uint2* __restrict__ Bf, int bFS,
    float* __restrict__ C, int ldc, int cBS,
    int M, int K, const float* __restrict__ bias, int mode, float scale)
{
    extern __shared__ char smem_raw[];
    float (*As)[128][36] = reinterpret_cast<float(*)[128][36]>(smem_raw);
    uint2* Bs = reinterpret_cast<uint2*>(smem_raw + 2 * 128 * 36 * 4);
    const float* Ab  = A  + (size_t)blockIdx.z * aBS;
    const uint2* Bfb = Bf + (size_t)blockIdx.z * bFS;
    float*       Cb  = C  + (size_t)blockIdx.z * cBS;
    int row0 = blockIdx.x * 128;
    int tid = threadIdx.x, w = tid >> 5, lane = tid & 31;
    int g = lane >> 2, t4 = lane & 3;
    int sk = (tid & 7) * 4, srr = tid >> 3;

    float d[8][4];
    #pragma unroll
    for (int i = 0; i < 8; i++)
        #pragma unroll
        for (int j = 0; j < 4; j++) d[i][j] = 0.f;

    auto stage = [&](int buf, int kk) {
        #pragma unroll
        for (int p = 0; p < 4; p++) {
            int r = p * 32 + srr;
            int gr = row0 + r;
            uint32_t sa = (uint32_t)__cvta_generic_to_shared(&As[buf][r][sk]);
            const float* gp = Ab + (size_t)gr * lda + kk + sk;
            int sz = (gr < M) ? 16 : 0;
            asm volatile("cp.async.cg.shared.global [%0], [%1], 16, %2;\n"
                         :: "r"(sa), "l"(gp), "r"(sz));
        }
        const uint2* bsrc = Bfb + (size_t)(kk >> 3) * 256 + tid;
        #pragma unroll
        for (int j = 0; j < 4; j++) {
            uint32_t sa = (uint32_t)__cvta_generic_to_shared(&Bs[buf * 1024 + tid + 256 * j]);
            asm volatile("cp.async.ca.shared.global [%0], [%1], 8;\n"
                         :: "r"(sa), "l"(bsrc + 256 * j));
        }
        asm volatile("cp.async.commit_group;\n");
    };

    stage(0, 0);
    int buf = 0;
    for (int kk = 0; kk < K; kk += 32) {
        if (kk + 32 < K) {
            stage(buf ^ 1, kk + 32);
            asm volatile("cp.async.wait_group 1;\n");
        } else {
            asm volatile("cp.async.wait_group 0;\n");
        }
        __syncthreads();

        const uint4* Bs4 = (const uint4*)(Bs + buf * 1024);
        #pragma unroll
        for (int k8 = 0; k8 < 4; k8++) {
            int kb = k8 * 8;
            float a0 = As[buf][w * 16 + g][kb + t4];
            float a1 = As[buf][w * 16 + g + 8][kb + t4];
            float a2 = As[buf][w * 16 + g][kb + t4 + 4];
            float a3 = As[buf][w * 16 + g + 8][kb + t4 + 4];
            uint32_t ah0, al0, ah1, al1, ah2, al2, ah3, al3;
            if (PASSES == 2) {
                split_tf32(a0, ah0, al0);
                split_tf32(a1, ah1, al1);
                split_tf32(a2, ah2, al2);
                split_tf32(a3, ah3, al3);
            } else {
                ah0 = to_tf32(a0); ah1 = to_tf32(a1);
                ah2 = to_tf32(a2); ah3 = to_tf32(a3);
            }
            #pragma unroll
            for (int np = 0; np < 4; np++) {
                uint4 bb = Bs4[(k8 * 4 + np) * 32 + lane];
                if (PASSES == 2) {
                    mma8(d[2 * np],     al0, al1, al2, al3, bb.x, bb.y);
                    mma8(d[2 * np + 1], al0, al1, al2, al3, bb.z, bb.w);
                }
                mma8(d[2 * np],     ah0, ah1, ah2, ah3, bb.x, bb.y);
                mma8(d[2 * np + 1], ah0, ah1, ah2, ah3, bb.z, bb.w);
            }
        }
        __syncthreads();   // protect buf before it is re-staged next iteration
        buf ^= 1;
    }

    int rb = row0 + w * 16;
    int rA = rb + g, rB = rb + g + 8;
    #pragma unroll
    for (int nt = 0; nt < 8; nt++) {
        int c = nt * 8 + t4 * 2;
        if (rA < M) {
            float2 v = make_float2(d[nt][0], d[nt][1]);
            if (mode == 2) {
                __half2 hh = __floats2half2_rn(v.x, v.y);
                ((uint32_t*)Cb)[((size_t)rA * 32 + (c >> 1)) * 2 + 1] = *(uint32_t*)&hh;
            } else {
                if (mode == 1) { v.x = lrelu(scale * v.x, 0.01f); v.y = lrelu(scale * v.y, 0.01f); }
                else if (bias) { v.x += bias[c]; v.y += bias[c + 1]; }
                *(float2*)&Cb[(size_t)rA * ldc + c] = v;
            }
        }
        if (rB < M) {
            float2 v = make_float2(d[nt][2], d[nt][3]);
            if (mode == 2) {
                __half2 hh = __floats2half2_rn(v.x, v.y);
                ((uint32_t*)Cb)[((size_t)rB * 32 + (c >> 1)) * 2 + 1] = *(uint32_t*)&hh;
            } else {
                if (mode == 1) { v.x = lrelu(scale * v.x, 0.01f); v.y = lrelu(scale * v.y, 0.01f); }
                else if (bias) { v.x += bias[c]; v.y += bias[c + 1]; }
                *(float2*)&Cb[(size_t)rB * ldc + c] = v;
            }
        }
    }
}

// ---------------- both layers at once: bl[i][h]=We@a_l[i,h], br[i][h]=We@a_r[i,h] ----------------
__global__ void k_vecs2(const float* __restrict__ We,
                        const float* __restrict__ al, const float* __restrict__ ar) {
    int i = blockIdx.x;             // layer
    int t = threadIdx.x;
    int h = t >> 6, k = t & 63;
    float sl = 0.f, sr = 0.f;
    #pragma unroll 8
    for (int d = 0; d < 64; d++) {
        float w = We[k * 64 + d];
        sl += w * al[i * 256 + h * 64 + d];
        sr += w * ar[i * 256 + h * 64 + d];
    }
    g_bl[i * 256 + h * 64 + k] = sl;
    g_br[i * 256 + h * 64 + k] = sr;
}

// ---------------- prep: fp16 pack of cur (x-word only) + el/er dots. warp per node ----------------
__global__ __launch_bounds__(256) void k_prep(const float* __restrict__ cur, int lda, int layer) {
    __shared__ float blS[256], brS[256];
    int tid = threadIdx.x;
    blS[tid] = g_bl[layer * 256 + tid];
    brS[tid] = g_br[layer * 256 + tid];
    __syncthreads();
    int w = tid >> 5, lane = tid & 31;
    int n = blockIdx.x * 8 + w;
    float2 c = *(const float2*)&cur[(size_t)n * lda + lane * 2];
    __half2 ch = __floats2half2_rn(c.x, c.y);
    ((uint32_t*)&g_h2[n * 32 + lane])[0] = *(uint32_t*)&ch;   // .y (pooled) written by GEMM mode 2
    float p[8];
    #pragma unroll
    for (int h = 0; h < 4; h++) {
        p[h]     = c.x * blS[h * 64 + 2 * lane] + c.y * blS[h * 64 + 2 * lane + 1];
        p[4 + h] = c.x * brS[h * 64 + 2 * lane] + c.y * brS[h * 64 + 2 * lane + 1];
    }
    #pragma unroll
    for (int o = 16; o; o >>= 1) {
        #pragma unroll
        for (int q = 0; q < 8; q++) p[q] += __shfl_xor_sync(0xffffffffu, p[q], o);
    }
    if (lane == 0) {
        ((float4*)g_el)[n] = make_float4(p[0], p[1], p[2], p[3]);
        ((float4*)g_er)[n] = make_float4(p[4], p[5], p[6], p[7]);
    }
}

// ---------------- fused per-dst softmax (no-max) + aggregation + GaAN gate (pre-applied) ----------------
// Warp per dst. 2-wide batched 8B gathers, scalar FMA accumulation. No atomics.
__global__ __launch_bounds__(256) void k_agg(const float* __restrict__ Wg,
                                             const float* __restrict__ bg) {
    __shared__ float  WgS[768];
    __shared__ int    ssh[8][32];
    __shared__ float4 wsh[8][32];
    int tid = threadIdx.x, w = tid >> 5, lane = tid & 31;
    #pragma unroll
    for (int i = 0; i < 3; i++) WgS[tid + 256 * i] = Wg[tid + 256 * i];
    __syncthreads();
    int d = blockIdx.x * 8 + w;
    int r0 = g_rowptr[d], r1 = g_rowptr[d + 1];
    float4 erv = ((const float4*)g_er)[d];

    float s0 = 0.f, s1 = 0.f, s2 = 0.f, s3 = 0.f;
    float2 a0 = {0, 0}, a1 = {0, 0}, a2 = {0, 0}, a3 = {0, 0}, am = {0, 0};
    float2 amx = {-1e30f, -1e30f};
    int l2 = lane * 2;
    for (int base = r0; base < r1; base += 32) {
        int cnt = min(32, r1 - base);
        if (lane < cnt) {
            int s = g_col[base + lane];
            float4 e = ((const float4*)g_el)[s];
            float4 wv;
            wv.x = __expf(lrelu(e.x + erv.x, 0.2f));
            wv.y = __expf(lrelu(e.y + erv.y, 0.2f));
            wv.z = __expf(lrelu(e.z + erv.z, 0.2f));
            wv.w = __expf(lrelu(e.w + erv.w, 0.2f));
            s0 += wv.x; s1 += wv.y; s2 += wv.z; s3 += wv.w;
            ssh[w][lane] = s;
            wsh[w][lane] = wv;
        }
        __syncwarp();
        int t = 0;
        for (; t + 1 < cnt; t += 2) {
            int sa = ssh[w][t], sb = ssh[w][t + 1];
            uint2 hva = __ldg(&g_h2[(size_t)sa * 32 + lane]);
            uint2 hvb = __ldg(&g_h2[(size_t)sb * 32 + lane]);
            float4 wva = wsh[w][t];
            float4 wvb = wsh[w][t + 1];
            float2 ca  = __half22float2(*(__half2*)&hva.x);
            float2 ppa = __half22float2(*(__half2*)&hva.y);
            a0.x += wva.x * ca.x; a0.y += wva.x * ca.y;
            a1.x += wva.y * ca.x; a1.y += wva.y * ca.y;
            a2.x += wva.z * ca.x; a2.y += wva.z * ca.y;
            a3.x += wva.w * ca.x; a3.y += wva.w * ca.y;
            am.x += ca.x;         am.y += ca.y;
            amx.x = fmaxf(amx.x, ppa.x);
            amx.y = fmaxf(amx.y, ppa.y);
            float2 cb  = __half22float2(*(__half2*)&hvb.x);
            float2 ppb = __half22float2(*(__half2*)&hvb.y);
            a0.x += wvb.x * cb.x; a0.y += wvb.x * cb.y;
            a1.x += wvb.y * cb.x; a1.y += wvb.y * cb.y;
            a2.x += wvb.z * cb.x; a2.y += wvb.z * cb.y;
            a3.x += wvb.w * cb.x; a3.y += wvb.w * cb.y;
            am.x += cb.x;         am.y += cb.y;
            amx.x = fmaxf(amx.x, ppb.x);
            amx.y = fmaxf(amx.y, ppb.y);
        }
        if (t < cnt) {
            int s = ssh[w][t];
            float4 wv = wsh[w][t];
            uint2 hv = __ldg(&g_h2[(size_t)s * 32 + lane]);
            float2 c  = __half22float2(*(__half2*)&hv.x);
            float2 pp = __half22float2(*(__half2*)&hv.y);
            a0.x += wv.x * c.x; a0.y += wv.x * c.y;
            a1.x += wv.y * c.x; a1.y += wv.y * c.y;
            a2.x += wv.z * c.x; a2.y += wv.z * c.y;
            a3.x += wv.w * c.x; a3.y += wv.w * c.y;
            am.x += c.x;        am.y += c.y;
            amx.x = fmaxf(amx.x, pp.x);
            amx.y = fmaxf(amx.y, pp.y);
        }
        __syncwarp();
    }
    #pragma unroll
    for (int o = 16; o; o >>= 1) {
        s0 += __shfl_xor_sync(0xffffffffu, s0, o);
        s1 += __shfl_xor_sync(0xffffffffu, s1, o);
        s2 += __shfl_xor_sync(0xffffffffu, s2, o);
        s3 += __shfl_xor_sync(0xffffffffu, s3, o);
    }
    float dinv = 1.f / (float)(r1 - r0);

    // GaAN gate: g = sigmoid([cur_d, mx, mn] @ Wg + bg)
    float2 cd = __half22float2(*(__half2*)&g_h2[(size_t)d * 32 + lane].x);
    float gin[6] = {cd.x, cd.y, amx.x, amx.y, am.x * dinv, am.y * dinv};
    int   kbase[3] = {l2, 64 + l2, 128 + l2};
    float gp0 = 0.f, gp1 = 0.f, gp2 = 0.f, gp3 = 0.f;
    #pragma unroll
    for (int q = 0; q < 3; q++) {
        #pragma unroll
        for (int e2 = 0; e2 < 2; e2++) {
            float v = gin[q * 2 + e2];
            float4 wr = *(const float4*)&WgS[(kbase[q] + e2) * 4];
            gp0 += v * wr.x; gp1 += v * wr.y; gp2 += v * wr.z; gp3 += v * wr.w;
        }
    }
    #pragma unroll
    for (int o = 16; o; o >>= 1) {
        gp0 += __shfl_xor_sync(0xffffffffu, gp0, o);
        gp1 += __shfl_xor_sync(0xffffffffu, gp1, o);
        gp2 += __shfl_xor_sync(0xffffffffu, gp2, o);
        gp3 += __shfl_xor_sync(0xffffffffu, gp3, o);
    }
    float g0 = 1.f / (1.f + __expf(-(gp0 + bg[0])));
    float g1 = 1.f / (1.f + __expf(-(gp1 + bg[1])));
    float g2 = 1.f / (1.f + __expf(-(gp2 + bg[2])));
    float g3 = 1.f / (1.f + __expf(-(gp3 + bg[3])));

    float i0 = g0 / s0, i1 = g1 / s1, i2 = g2 / s2, i3 = g3 / s3;
    float* ap = &g_acc[d * 256];
    *(float2*)&ap[l2]       = make_float2(a0.x * i0, a0.y * i0);
    *(float2*)&ap[64 + l2]  = make_float2(a1.x * i1, a1.y * i1);
    *(float2*)&ap[128 + l2] = make_float2(a2.x * i2, a2.y * i2);
    *(float2*)&ap[192 + l2] = make_float2(a3.x * i3, a3.y * i3);
}

// ---------------- launch: fork-join streams so CSR build hides under the proj GEMM ----------------
extern "C" void kernel_launch(void* const* d_in, const int* in_sizes, int n_in,
                              void* d_out, int out_size) {
    const float* ft    = (const float*)d_in[0];
    const float* Wp    = (const float*)d_in[1];
    const float* We    = (const float*)d_in[2];
    const float* a_l   = (const float*)d_in[3];
    const float* a_r   = (const float*)d_in[4];
    const float* Wv    = (const float*)d_in[5];
    const float* Wgp   = (const float*)d_in[6];
    const float* Wgate = (const float*)d_in[7];
    const float* bgate = (const float*)d_in[8];
    const float* Wtran = (const float*)d_in[9];
    const float* btran = (const float*)d_in[10];
    const int*   src   = (const int*)d_in[11];
    const int*   dst   = (const int*)d_in[12];
    int ne = in_sizes[11];
    float* out = (float*)d_out;

    float *p_hcat, *p_curA, *p_acc;
    uint2* p_bfrag;
    uint2* p_h2;
    cudaGetSymbolAddress((void**)&p_hcat, g_hcat);
    cudaGetSymbolAddress((void**)&p_curA, g_curA);
    cudaGetSymbolAddress((void**)&p_acc, g_acc);
    cudaGetSymbolAddress((void**)&p_bfrag, g_bfrag);
    cudaGetSymbolAddress((void**)&p_h2, g_h2);

    cudaFuncSetAttribute(k_mma<2>, cudaFuncAttributeMaxDynamicSharedMemorySize, MMA_SMEM);
    cudaFuncSetAttribute(k_mma<1>, cudaFuncAttributeMaxDynamicSharedMemorySize, MMA_SMEM);

    const int MB = (NN + 127) / 128;  // 391
    int eb = (ne + 255) / 256;

    // side stream for the independent CSR build + attention-vector precompute
    cudaStream_t s2;
    cudaStreamCreateWithFlags(&s2, cudaStreamNonBlocking);
    cudaEvent_t evFork, evVecs, evCsr;
    cudaEventCreateWithFlags(&evFork, cudaEventDisableTiming);
    cudaEventCreateWithFlags(&evVecs, cudaEventDisableTiming);
    cudaEventCreateWithFlags(&evCsr, cudaEventDisableTiming);

    // fork
    cudaEventRecord(evFork, 0);
    cudaStreamWaitEvent(s2, evFork, 0);

    // side stream: vecs2 then CSR chain
    k_vecs2<<<2, 256, 0, s2>>>(We, a_l, a_r);
    cudaEventRecord(evVecs, s2);
    k_zero_deg<<<(NN + 255) / 256, 256, 0, s2>>>();
    k_deg<<<eb, 256, 0, s2>>>(dst, ne);
    k_scan1<<<SCB, 1024, 0, s2>>>();
    k_scan2<<<1, 64, 0, s2>>>();
    k_scan3<<<SCB, 1024, 0, s2>>>();
    k_fill<<<eb, 256, 0, s2>>>(src, dst, ne);
    cudaEventRecord(evCsr, s2);

    // main stream: weight split + proj GEMM + layer-0 pooled (independent of CSR)
    k_splitAll<<<(FR_TOTAL / 2 + 255) / 256, 256>>>(Wp, Wgp, Wv, Wtran);
    // proj_feat = ft @ Wp -> hcat[:,0:64)   (1xTF32)
    k_mma<1><<<dim3(MB, 1, 1), 256, MMA_SMEM>>>(ft, 512, 0, p_bfrag + FR_WP, 0, p_hcat, 320, 0, NN, 512, nullptr, 0, 1.f);

    for (int i = 0; i < 2; i++) {
        const float* cur = i ? p_curA : p_hcat;
        int lda = i ? 64 : 320;
        // pooled = cur @ Wg_pool[i], fp16 into g_h2[..].y (mode 2, 1xTF32)
        k_mma<1><<<dim3(MB, 1, 1), 256, MMA_SMEM>>>(cur, lda, 0, p_bfrag + (i ? FR_WGP1 : FR_WGP0), 0,
                                                    (float*)p_h2, 0, 0, NN, 64, nullptr, 2, 1.f);
        if (i == 0) cudaStreamWaitEvent(0, evVecs, 0);   // prep needs g_bl/g_br
        k_prep<<<6250, 256>>>(cur, lda, i);
        if (i == 0) cudaStreamWaitEvent(0, evCsr, 0);    // agg needs CSR
        k_agg<<<6250, 256>>>(Wgate + i * 768, bgate + i * 4);
        if (i == 0) {
            // cur1 = lrelu(0.25 * acc_gated @ Wv0_stacked[256,64])  (1xTF32)
            k_mma<1><<<dim3(MB, 1, 1), 256, MMA_SMEM>>>(p_acc, 256, 0, p_bfrag + FR_WV0, 0,
                                                        p_curA, 64, 0, NN, 256, nullptr, 1, 0.25f);
        } else {
            // hcat[:,64+h*64+:] = lrelu(acc_gated[:,h,:] @ Wv1_h)   (1xTF32, batched over heads)
            k_mma<1><<<dim3(MB, 1, 4), 256, MMA_SMEM>>>(p_acc, 256, 64, p_bfrag + FR_WV1, 2048,
                                                        p_hcat + 64, 320, 64, NN, 64, nullptr, 1, 1.f);
        }
    }

    // out = hcat[N,320] @ Wtran[320,64] + btran  (1xTF32)
    k_mma<1><<<dim3(MB, 1, 1), 256, MMA_SMEM>>>(p_hcat, 320, 0, p_bfrag + FR_WT, 0, out, 64, 0, NN, 320, btran, 0, 1.f);
}